// round 12
// baseline (speedup 1.0000x reference)
#include <cuda_runtime.h>
#include <cuda_bf16.h>
#include <math.h>
#include <stdint.h>

typedef __nv_bfloat16 bf16;

#define TOK   16384
#define DIMD  1024
#define HIDD  2048
#define QKD   128
#define GRP   256
#define NGRP  64
#define NPB   4096

// ---------------- device scratch ----------------
__device__ float g_normed[TOK * DIMD];              // tf32-rounded (G2 operand)
__device__ bf16  g_normedb[TOK * DIMD];             // bf16 copy (G1 operand)
__device__ bf16  g_Whb[2 * HIDD * DIMD];            // W_h transposed [n][k] bf16
__device__ bf16  g_Wob[DIMD * HIDD];                // W_out transposed [n][k] bf16
__device__ float g_Wqkr[DIMD * QKD];                // W_qk tf32-rounded
__device__ float g_v[TOK * HIDD];                   // tf32-rounded (QUAD/LKV operand)
__device__ float g_gate[TOK * HIDD];                // fp32 (output-product path!)
__device__ float g_qq[TOK * QKD];
__device__ float g_lq[TOK * QKD];
__device__ float g_qkh[TOK * QKD];
__device__ float g_lkh[TOK * QKD];
__device__ float g_bias[GRP * GRP];
__device__ float g_attn[(size_t)NGRP * GRP * GRP];
__device__ float g_lkv_part[16][QKD * HIDD];
__device__ float g_lkv[4 * QKD * HIDD];             // tf32-rounded
__device__ bf16  g_gatedb[TOK * HIDD];              // bf16 (FIN operand; measured-safe)

__device__ __forceinline__ float rna_tf32(float x) {
    float y;
    asm("cvt.rna.tf32.f32 %0, %1;\n" : "=f"(y) : "f"(x));
    return y;
}

// ---------------- small kernels ----------------

__global__ void bias_kernel(const float* __restrict__ rel_emb) {
    int idx = blockIdx.x * blockDim.x + threadIdx.x;
    int i = idx >> 8, j = idx & 255;
    int n = i - j;
    int ret = (n < 0) ? 16 : 0;
    int na = abs(n);
    int bucket;
    if (na < 8) {
        bucket = ret + na;
    } else {
        float t = logf((float)na * 0.125f) / 2.7725887298583984f;
        t = t * 8.0f;
        float r = rintf(t);
        int ti = (fabsf(t - r) < 1e-3f) ? (int)r : (int)t;
        int vl = 8 + ti;
        if (vl > 15) vl = 15;
        bucket = ret + vl;
    }
    g_bias[idx] = rel_emb[bucket] * 11.313708498984761f;
}

// 32x32 tiled transpose+convert: src f32 [K][N] -> dst bf16 [N][K]
__global__ void wtrans_kernel(const float* __restrict__ src, int which, int K, int N) {
    bf16* dst = (which == 0) ? g_Whb : g_Wob;
    __shared__ float t[32][33];
    int n0 = blockIdx.x * 32, k0 = blockIdx.y * 32;
    int tx = threadIdx.x, ty = threadIdx.y;
    #pragma unroll
    for (int i = 0; i < 4; i++)
        t[ty + 8*i][tx] = src[(size_t)(k0 + ty + 8*i) * N + n0 + tx];
    __syncthreads();
    #pragma unroll
    for (int i = 0; i < 4; i++)
        dst[(size_t)(n0 + ty + 8*i) * K + k0 + tx] = __float2bfloat16(t[tx][ty + 8*i]);
}

__global__ void wqk_round_kernel(const float* __restrict__ src) {
    int i = blockIdx.x * blockDim.x + threadIdx.x;
    g_Wqkr[i] = rna_tf32(src[i]);
}

__global__ void ln_kernel(const float* __restrict__ x,
                          const float* __restrict__ gw,
                          const float* __restrict__ bw) {
    int row = blockIdx.x;
    int t = threadIdx.x;
    const float4* xr = (const float4*)(x + (size_t)row * DIMD);
    float4 v = xr[t];
    float s  = v.x + v.y + v.z + v.w;
    float s2 = v.x*v.x + v.y*v.y + v.z*v.z + v.w*v.w;
    #pragma unroll
    for (int o = 16; o; o >>= 1) {
        s  += __shfl_xor_sync(0xffffffffu, s,  o);
        s2 += __shfl_xor_sync(0xffffffffu, s2, o);
    }
    __shared__ float sm[8], sm2[8];
    int w = t >> 5;
    if ((t & 31) == 0) { sm[w] = s; sm2[w] = s2; }
    __syncthreads();
    float ts = 0.f, ts2 = 0.f;
    #pragma unroll
    for (int k = 0; k < 8; k++) { ts += sm[k]; ts2 += sm2[k]; }
    float mu   = ts  * (1.0f / DIMD);
    float var  = ts2 * (1.0f / DIMD) - mu * mu;
    float rstd = rsqrtf(var + 1e-5f);
    float4 gv = ((const float4*)gw)[t];
    float4 bv = ((const float4*)bw)[t];
    float o0 = (v.x - mu) * rstd * gv.x + bv.x;
    float o1 = (v.y - mu) * rstd * gv.y + bv.y;
    float o2 = (v.z - mu) * rstd * gv.z + bv.z;
    float o3 = (v.w - mu) * rstd * gv.w + bv.w;
    float4 o; o.x = rna_tf32(o0); o.y = rna_tf32(o1); o.z = rna_tf32(o2); o.w = rna_tf32(o3);
    ((float4*)(g_normed + (size_t)row * DIMD))[t] = o;
    bf16* ob = g_normedb + (size_t)row * DIMD + t * 4;
    ob[0] = __float2bfloat16(o0); ob[1] = __float2bfloat16(o1);
    ob[2] = __float2bfloat16(o2); ob[3] = __float2bfloat16(o3);
}

__global__ void lkv_reduce_kernel() {
    int idx = blockIdx.x * blockDim.x + threadIdx.x;
    int b = idx >> 18;
    int r = idx & ((1 << 18) - 1);
    float s = g_lkv_part[b*4+0][r] + g_lkv_part[b*4+1][r]
            + g_lkv_part[b*4+2][r] + g_lkv_part[b*4+3][r];
    g_lkv[idx] = rna_tf32(s * (1.0f / NPB));
}

// ---------------- shared helpers ----------------

enum { M_G1 = 0, M_G2, M_SIM, M_LKV, M_FIN };

__device__ __forceinline__ float siluf(float x) { return x / (1.0f + expf(-x)); }

__device__ __forceinline__ void cpa16(void* dst, const void* src) {
    uint32_t d = (uint32_t)__cvta_generic_to_shared(dst);
    asm volatile("cp.async.cg.shared.global [%0], [%1], 16;\n" :: "r"(d), "l"(src));
}

// ---------------- TF32 GEMM (G2 / SIM / LKV): 128x128, 2-stage ----------------

template<int MODE>
__device__ __forceinline__ void epi(int r, int c, float a, int z,
                                    const float* p0, const float* p1,
                                    const float* p2) {
    if constexpr (MODE == M_G2) {
        float q = siluf(a + p0[c]);
        size_t o = (size_t)r * QKD + c;
        g_qq[o]  = rna_tf32(q * p1[0*QKD + c] + p2[0*QKD + c]);
        g_lq[o]  = rna_tf32(q * p1[1*QKD + c] + p2[1*QKD + c]);
        g_qkh[o] = rna_tf32(q * p1[2*QKD + c] + p2[2*QKD + c]);
        g_lkh[o] = rna_tf32(q * p1[3*QKD + c] + p2[3*QKD + c]);
    } else if constexpr (MODE == M_SIM) {
        float s = a * (1.0f / GRP) + g_bias[r * GRP + c];
        s = fmaxf(s, 0.0f);
        g_attn[(size_t)z * GRP * GRP + r * GRP + c] = rna_tf32(s * s);
    } else if constexpr (MODE == M_LKV) {
        g_lkv_part[z][r * HIDD + c] = a;
    }
}

#define TSTRIDE 4608

template<int MODE>
__global__ void __launch_bounds__(256, 2)
gemm_kernel(const float* __restrict__ p0, const float* __restrict__ p1,
            const float* __restrict__ p2) {
    const float* A; const float* B; int K, lda, ldb;
    int z = blockIdx.z;
    if constexpr (MODE == M_G2)       { A = g_normed; B = g_Wqkr; K = DIMD; lda = DIMD; ldb = QKD; }
    else if constexpr (MODE == M_SIM) { A = g_qq  + (size_t)z*GRP*QKD; B = g_qkh + (size_t)z*GRP*QKD; K = QKD; lda = QKD; ldb = QKD; }
    else                              { int b = z >> 2, ks = z & 3;
                                        A = g_lkh + (size_t)(b*NPB + ks*1024)*QKD;
                                        B = g_v   + (size_t)(b*NPB + ks*1024)*HIDD;
                                        K = 1024; lda = QKD; ldb = HIDD; }

    constexpr bool TA = (MODE == M_LKV);   // A stored K x M  -> smem [k][m]
    constexpr bool TB = (MODE == M_SIM);   // B stored N x K  -> smem [n][k]

    extern __shared__ float smem[];
    float* Abuf = smem;
    float* Bbuf = smem + 2 * TSTRIDE;

    int tid = threadIdx.x;
    int m0 = blockIdx.y * 128, n0 = blockIdx.x * 128;
    int wid = tid >> 5, lane = tid & 31;
    int wm = (wid >> 2) * 64, wn = (wid & 3) * 32;
    int gq = lane >> 2, tg = lane & 3;

    auto load_tiles = [&](int stage, int k0) {
        float* As = Abuf + stage * TSTRIDE;
        float* Bs = Bbuf + stage * TSTRIDE;
        if constexpr (!TA) {
            #pragma unroll
            for (int r = 0; r < 4; r++) {
                int chunk = tid + r * 256;
                int row = chunk >> 3, cc = (chunk & 7) * 4;
                cpa16(&As[row * 36 + cc], A + (size_t)(m0 + row) * lda + k0 + cc);
            }
        } else {
            #pragma unroll
            for (int r = 0; r < 4; r++) {
                int chunk = tid + r * 256;
                int row = chunk >> 5, cc = (chunk & 31) * 4;
                cpa16(&As[row * 132 + cc], A + (size_t)(k0 + row) * lda + m0 + cc);
            }
        }
        if constexpr (TB) {
            #pragma unroll
            for (int r = 0; r < 4; r++) {
                int chunk = tid + r * 256;
                int row = chunk >> 3, cc = (chunk & 7) * 4;
                cpa16(&Bs[row * 36 + cc], B + (size_t)(n0 + row) * ldb + k0 + cc);
            }
        } else {
            #pragma unroll
            for (int r = 0; r < 4; r++) {
                int chunk = tid + r * 256;
                int row = chunk >> 5, cc = (chunk & 31) * 4;
                cpa16(&Bs[row * 132 + cc], B + (size_t)(k0 + row) * ldb + n0 + cc);
            }
        }
    };

    float acc[4][4][4];
    #pragma unroll
    for (int i = 0; i < 4; i++)
        #pragma unroll
        for (int j = 0; j < 4; j++)
            #pragma unroll
            for (int k = 0; k < 4; k++) acc[i][j][k] = 0.0f;

    int nK = K >> 5;
    load_tiles(0, 0);
    asm volatile("cp.async.commit_group;\n" ::);

    int s = 0;
    for (int i = 0; i < nK; i++) {
        asm volatile("cp.async.wait_group 0;\n" ::);
        __syncthreads();
        if (i + 1 < nK) {
            load_tiles(s ^ 1, (i + 1) * 32);
            asm volatile("cp.async.commit_group;\n" ::);
        }

        const float* As = Abuf + s * TSTRIDE;
        const float* Bs = Bbuf + s * TSTRIDE;

        #pragma unroll
        for (int ks = 0; ks < 32; ks += 8) {
            uint32_t af[4][4], bfr[4][2];
            #pragma unroll
            for (int mt = 0; mt < 4; mt++) {
                int r0 = wm + mt * 16 + gq;
                if constexpr (!TA) {
                    af[mt][0] = *(const uint32_t*)&As[(r0    ) * 36 + ks + tg];
                    af[mt][1] = *(const uint32_t*)&As[(r0 + 8) * 36 + ks + tg];
                    af[mt][2] = *(const uint32_t*)&As[(r0    ) * 36 + ks + tg + 4];
                    af[mt][3] = *(const uint32_t*)&As[(r0 + 8) * 36 + ks + tg + 4];
                } else {
                    af[mt][0] = *(const uint32_t*)&As[(ks + tg    ) * 132 + r0];
                    af[mt][1] = *(const uint32_t*)&As[(ks + tg    ) * 132 + r0 + 8];
                    af[mt][2] = *(const uint32_t*)&As[(ks + tg + 4) * 132 + r0];
                    af[mt][3] = *(const uint32_t*)&As[(ks + tg + 4) * 132 + r0 + 8];
                }
            }
            #pragma unroll
            for (int nt = 0; nt < 4; nt++) {
                int c0 = wn + nt * 8 + gq;
                if constexpr (TB) {
                    bfr[nt][0] = *(const uint32_t*)&Bs[c0 * 36 + ks + tg];
                    bfr[nt][1] = *(const uint32_t*)&Bs[c0 * 36 + ks + tg + 4];
                } else {
                    bfr[nt][0] = *(const uint32_t*)&Bs[(ks + tg    ) * 132 + c0];
                    bfr[nt][1] = *(const uint32_t*)&Bs[(ks + tg + 4) * 132 + c0];
                }
            }
            #pragma unroll
            for (int mt = 0; mt < 4; mt++)
                #pragma unroll
                for (int nt = 0; nt < 4; nt++) {
                    asm volatile(
                        "mma.sync.aligned.m16n8k8.row.col.f32.tf32.tf32.f32 "
                        "{%0,%1,%2,%3},{%4,%5,%6,%7},{%8,%9},{%0,%1,%2,%3};\n"
                        : "+f"(acc[mt][nt][0]), "+f"(acc[mt][nt][1]),
                          "+f"(acc[mt][nt][2]), "+f"(acc[mt][nt][3])
                        : "r"(af[mt][0]), "r"(af[mt][1]), "r"(af[mt][2]), "r"(af[mt][3]),
                          "r"(bfr[nt][0]), "r"(bfr[nt][1]));
                }
        }
        s ^= 1;
    }

    #pragma unroll
    for (int mt = 0; mt < 4; mt++)
        #pragma unroll
        for (int nt = 0; nt < 4; nt++) {
            int r0 = m0 + wm + mt * 16 + gq;
            int c0 = n0 + wn + nt * 8 + tg * 2;
            epi<MODE>(r0,     c0,     acc[mt][nt][0], z, p0, p1, p2);
            epi<MODE>(r0,     c0 + 1, acc[mt][nt][1], z, p0, p1, p2);
            epi<MODE>(r0 + 8, c0,     acc[mt][nt][2], z, p0, p1, p2);
            epi<MODE>(r0 + 8, c0 + 1, acc[mt][nt][3], z, p0, p1, p2);
        }
}

// ---------- fused QUAD+LOUT (tf32): 256x128 tile (full group), 8 warps ----------

#define QLA 9216    // A floats per stage: 256*36
#define QLB 4224    // B floats per stage: 32*132
#define SMEM_QL ((QLA + QLB) * 2 * 4)   // 107520

__global__ void __launch_bounds__(256, 1)
gemm_ql_kernel() {
    int z = blockIdx.z;          // group 0..63
    int b = z >> 4;              // batch
    const float* A1 = g_attn + (size_t)z * GRP * GRP;   // [m][k], lda GRP
    const float* B1 = g_v    + (size_t)z * GRP * HIDD;  // [k][n], ldb HIDD
    const float* A2 = g_lq   + (size_t)z * GRP * QKD;   // [m][k], lda QKD
    const float* B2 = g_lkv  + (size_t)b * QKD * HIDD;  // [k][n], ldb HIDD

    extern __shared__ float smem[];
    float* Abuf = smem;
    float* Bbuf = smem + 2 * QLA;

    int tid = threadIdx.x;
    int n0 = blockIdx.x * 128;                // m0 = 0 (whole group per CTA)
    int wid = tid >> 5, lane = tid & 31;
    int wm = (wid >> 1) * 64, wn = (wid & 1) * 64;
    int gq = lane >> 2, tg = lane & 3;

    auto load_tiles = [&](int stage, int slab) {
        float* As = Abuf + stage * QLA;
        float* Bs = Bbuf + stage * QLB;
        const float* A; const float* B; int lda, k0;
        if (slab < 8) { A = A1; lda = GRP; k0 = slab * 32; B = B1 + (size_t)k0 * HIDD; }
        else          { A = A2; lda = QKD; k0 = (slab - 8) * 32; B = B2 + (size_t)k0 * HIDD; }
        #pragma unroll
        for (int r = 0; r < 8; r++) {            // A: 256 rows x 8 chunks
            int chunk = tid + r * 256;
            int row = chunk >> 3, cc = (chunk & 7) * 4;
            cpa16(&As[row * 36 + cc], A + (size_t)row * lda + k0 + cc);
        }
        #pragma unroll
        for (int r = 0; r < 4; r++) {            // B: 32 rows x 32 chunks
            int chunk = tid + r * 256;
            int row = chunk >> 5, cc = (chunk & 31) * 4;
            cpa16(&Bs[row * 132 + cc], B + (size_t)row * HIDD + n0 + cc);
        }
    };

    float acc[4][8][4];
    #pragma unroll
    for (int i = 0; i < 4; i++)
        #pragma unroll
        for (int j = 0; j < 8; j++)
            #pragma unroll
            for (int k = 0; k < 4; k++) acc[i][j][k] = 0.0f;

    const int nSlab = 12;        // 8 (attn@v) + 4 (lq@lkv)
    load_tiles(0, 0);
    asm volatile("cp.async.commit_group;\n" ::);

    int s = 0;
    for (int i = 0; i < nSlab; i++) {
        asm volatile("cp.async.wait_group 0;\n" ::);
        __syncthreads();
        if (i + 1 < nSlab) {
            load_tiles(s ^ 1, i + 1);
            asm volatile("cp.async.commit_group;\n" ::);
        }

        const float* As = Abuf + s * QLA;
        const float* Bs = Bbuf + s * QLB;

        #pragma unroll
        for (int ks = 0; ks < 32; ks += 8) {
            uint32_t af[4][4], bfr[8][2];
            #pragma unroll
            for (int mt = 0; mt < 4; mt++) {
                int r0 = wm + mt * 16 + gq;
                af[mt][0] = *(const uint32_t*)&As[(r0    ) * 36 + ks + tg];
                af[mt][1] = *(const uint32_t*)&As[(r0 + 8) * 36 + ks + tg];
                af[mt][2] = *(const uint32_t*)&As[(r0    ) * 36 + ks + tg + 4];
                af[mt][3] = *(const uint32_t*)&As[(r0 + 8) * 36 + ks + tg + 4];
            }
            #pragma unroll
            for (int nt = 0; nt < 8; nt++) {
                int c0 = wn + nt * 8 + gq;
                bfr[nt][0] = *(const uint32_t*)&Bs[(ks + tg    ) * 132 + c0];
                bfr[nt][1] = *(const uint32_t*)&Bs[(ks + tg + 4) * 132 + c0];
            }
            #pragma unroll
            for (int mt = 0; mt < 4; mt++)
                #pragma unroll
                for (int nt = 0; nt < 8; nt++) {
                    asm volatile(
                        "mma.sync.aligned.m16n8k8.row.col.f32.tf32.tf32.f32 "
                        "{%0,%1,%2,%3},{%4,%5,%6,%7},{%8,%9},{%0,%1,%2,%3};\n"
                        : "+f"(acc[mt][nt][0]), "+f"(acc[mt][nt][1]),
                          "+f"(acc[mt][nt][2]), "+f"(acc[mt][nt][3])
                        : "r"(af[mt][0]), "r"(af[mt][1]), "r"(af[mt][2]), "r"(af[mt][3]),
                          "r"(bfr[nt][0]), "r"(bfr[nt][1]));
                }
        }
        s ^= 1;
    }

    #pragma unroll
    for (int mt = 0; mt < 4; mt++)
        #pragma unroll
        for (int nt = 0; nt < 8; nt++) {
            int r0 = wm + mt * 16 + gq;          // row within group (0..255)
            int c0 = n0 + wn + nt * 8 + tg * 2;
            #pragma unroll
            for (int e = 0; e < 4; e++) {
                int r = r0 + (e >> 1) * 8;
                int c = c0 + (e & 1);
                size_t o = ((size_t)z * GRP + r) * HIDD + c;
                g_gatedb[o] = __float2bfloat16(g_gate[o] * acc[mt][nt][e]);
            }
        }
}

// ---------- BF16 GEMM (G1, FIN): 256x128 tile, 8 warps, 3-stage + ldmatrix ----------

#define HA 10240    // A bf16 per stage: 256*40
#define HB 5120     // B bf16 per stage: 128*40
#define SMEM_BF ((HA + HB) * 3 * 2)   // 92160

template<int MODE>
__global__ void __launch_bounds__(256, 1)
gemm_bf16_kernel(const float* __restrict__ p0, const float* __restrict__ p2,
                 float* __restrict__ pf) {
    const bf16* A; const bf16* B; int K;
    if constexpr (MODE == M_G1) { A = g_normedb; B = g_Whb; K = DIMD; }
    else                        { A = g_gatedb;  B = g_Wob; K = HIDD; }

    extern __shared__ bf16 hsm[];
    bf16* Abuf = hsm;
    bf16* Bbuf = hsm + 3 * HA;

    int tid = threadIdx.x;
    int m0 = blockIdx.y * 256, n0 = blockIdx.x * 128;
    int wid = tid >> 5, lane = tid & 31;
    int wm = (wid >> 1) * 64, wn = (wid & 1) * 64;
    int gq = lane >> 2, tg = lane & 3;
    int lrow = lane & 7, lmat = lane >> 3;

    auto load_tiles = [&](int stage, int k0) {
        bf16* As = Abuf + stage * HA;
        bf16* Bs = Bbuf + stage * HB;
        #pragma unroll
        for (int r = 0; r < 4; r++) {            // A: 256 rows x 4 chunks
            int chunk = tid + r * 256;
            int row = chunk >> 2, cc = (chunk & 3) * 8;
            cpa16(&As[row * 40 + cc], A + (size_t)(m0 + row) * K + k0 + cc);
        }
        #pragma unroll
        for (int r = 0; r < 2; r++) {            // B: 128 rows x 4 chunks
            int chunk = tid + r * 256;
            int row = chunk >> 2, cc = (chunk & 3) * 8;
            cpa16(&Bs[row * 40 + cc], B + (size_t)(n0 + row) * K + k0 + cc);
        }
    };

    float acc[4][8][4];
    #pragma unroll
    for (int i = 0; i < 4; i++)
        #pragma unroll
        for (int j = 0; j < 8; j++)
            #pragma unroll
            for (int k = 0; k < 4; k++) acc[i][j][k] = 0.0f;

    int nK = K >> 5;
    load_tiles(0, 0);
    asm volatile("cp.async.commit_group;\n" ::);
    load_tiles(1, 32);
    asm volatile("cp.async.commit_group;\n" ::);

    for (int i = 0; i < nK; i++) {
        asm volatile("cp.async.wait_group 1;\n" ::);
        __syncthreads();
        if (i + 2 < nK) {
            load_tiles((i + 2) % 3, (i + 2) * 32);
            asm volatile("cp.async.commit_group;\n" ::);
        } else {
            asm volatile("cp.async.commit_group;\n" ::);
        }

        const bf16* As = Abuf + (i % 3) * HA;
        const bf16* Bs = Bbuf + (i % 3) * HB;

        #pragma unroll
        for (int ks = 0; ks < 32; ks += 16) {
            uint32_t af[4][4], bfr[8][2];
            #pragma unroll
            for (int mt = 0; mt < 4; mt++) {
                const bf16* p = &As[(size_t)(wm + mt * 16 + lrow + (lmat & 1) * 8) * 40
                                    + ks + (lmat >> 1) * 8];
                uint32_t addr = (uint32_t)__cvta_generic_to_shared(p);
                asm volatile(
                    "ldmatrix.sync.aligned.m8n8.x4.shared.b16 {%0,%1,%2,%3}, [%4];\n"
                    : "=r"(af[mt][0]), "=r"(af[mt][1]), "=r"(af[mt][2]), "=r"(af[mt][3])
                    : "r"(addr));
            }
            #pragma unroll
            for (int np = 0; np < 4; np++) {
                const bf16* p = &Bs[(size_t)(wn + np * 16 + lrow + (lmat >> 1) * 8) * 40
                                    + ks + (lmat & 1) * 8];
                uint32_t addr = (uint32_t)__cvta_generic_to_shared(p);
                asm volatile(
                    "ldmatrix.sync.aligned.m8n8.x4.shared.b16 {%0,%1,%2,%3}, [%4];\n"
                    : "=r"(bfr[2*np][0]), "=r"(bfr[2*np][1]),
                      "=r"(bfr[2*np+1][0]), "=r"(bfr[2*np+1][1])
                    : "r"(addr));
            }
            #pragma unroll
            for (int mt = 0; mt < 4; mt++)
                #pragma unroll
                for (int nt = 0; nt < 8; nt++) {
                    asm volatile(
                        "mma.sync.aligned.m16n8k16.row.col.f32.bf16.bf16.f32 "
                        "{%0,%1,%2,%3},{%4,%5,%6,%7},{%8,%9},{%0,%1,%2,%3};\n"
                        : "+f"(acc[mt][nt][0]), "+f"(acc[mt][nt][1]),
                          "+f"(acc[mt][nt][2]), "+f"(acc[mt][nt][3])
                        : "r"(af[mt][0]), "r"(af[mt][1]), "r"(af[mt][2]), "r"(af[mt][3]),
                          "r"(bfr[nt][0]), "r"(bfr[nt][1]));
                }
        }
    }

    #pragma unroll
    for (int mt = 0; mt < 4; mt++)
        #pragma unroll
        for (int nt = 0; nt < 8; nt++) {
            int r0 = m0 + wm + mt * 16 + gq;
            int c0 = n0 + wn + nt * 8 + tg * 2;
            #pragma unroll
            for (int e = 0; e < 4; e++) {
                int r = r0 + (e >> 1) * 8;
                int c = c0 + (e & 1);
                float a = acc[mt][nt][e];
                if constexpr (MODE == M_G1) {
                    float h = siluf(a + p0[c]);
                    if (c < HIDD) g_v[(size_t)r * HIDD + c] = rna_tf32(h);
                    else          g_gate[(size_t)r * HIDD + (c - HIDD)] = h;
                } else {
                    size_t o = (size_t)r * DIMD + c;
                    pf[o] = a + p0[c] + p2[o];
                }
            }
        }
}

#define SMEM_BYTES (4 * TSTRIDE * 4)   // 73728 for tf32 128-tile kernels

// ---------------- launch ----------------

extern "C" void kernel_launch(void* const* d_in, const int* in_sizes, int n_in,
                              void* d_out, int out_size) {
    const float* x     = (const float*)d_in[0];
    const float* ln_g  = (const float*)d_in[1];
    const float* ln_b  = (const float*)d_in[2];
    const float* W_h   = (const float*)d_in[3];
    const float* b_h   = (const float*)d_in[4];
    const float* W_qk  = (const float*)d_in[5];
    const float* b_qk  = (const float*)d_in[6];
    const float* gam   = (const float*)d_in[7];
    const float* bet   = (const float*)d_in[8];
    const float* rel   = (const float*)d_in[9];
    const float* W_out = (const float*)d_in[10];
    const float* b_out = (const float*)d_in[11];
    float* out = (float*)d_out;

    (void)in_sizes; (void)n_in; (void)out_size;

    static cudaStream_t s_side = nullptr;
    static cudaEvent_t ev_fork = nullptr, ev_prep = nullptr, ev_ln = nullptr,
                       ev_g2 = nullptr, ev_sim = nullptr;
    if (!s_side) {
        cudaStreamCreateWithFlags(&s_side, cudaStreamNonBlocking);
        cudaEventCreateWithFlags(&ev_fork, cudaEventDisableTiming);
        cudaEventCreateWithFlags(&ev_prep, cudaEventDisableTiming);
        cudaEventCreateWithFlags(&ev_ln,   cudaEventDisableTiming);
        cudaEventCreateWithFlags(&ev_g2,   cudaEventDisableTiming);
        cudaEventCreateWithFlags(&ev_sim,  cudaEventDisableTiming);
        cudaFuncSetAttribute(gemm_kernel<M_G2>,  cudaFuncAttributeMaxDynamicSharedMemorySize, SMEM_BYTES);
        cudaFuncSetAttribute(gemm_kernel<M_SIM>, cudaFuncAttributeMaxDynamicSharedMemorySize, SMEM_BYTES);
        cudaFuncSetAttribute(gemm_kernel<M_LKV>, cudaFuncAttributeMaxDynamicSharedMemorySize, SMEM_BYTES);
        cudaFuncSetAttribute(gemm_ql_kernel,     cudaFuncAttributeMaxDynamicSharedMemorySize, SMEM_QL);
        cudaFuncSetAttribute(gemm_bf16_kernel<M_G1>, cudaFuncAttributeMaxDynamicSharedMemorySize, SMEM_BF);
        cudaFuncSetAttribute(gemm_bf16_kernel<M_FIN>,cudaFuncAttributeMaxDynamicSharedMemorySize, SMEM_BF);
    }

    // fork; prep on side while ln runs on main
    cudaEventRecord(ev_fork, 0);
    cudaStreamWaitEvent(s_side, ev_fork, 0);

    wtrans_kernel<<<dim3(128, 32), dim3(32, 8), 0, s_side>>>(W_h, 0, DIMD, 2*HIDD);
    wtrans_kernel<<<dim3(32, 64),  dim3(32, 8), 0, s_side>>>(W_out, 1, HIDD, DIMD);
    wqk_round_kernel<<<(DIMD*QKD)/256, 256, 0, s_side>>>(W_qk);
    bias_kernel<<<(GRP*GRP)/256, 256, 0, s_side>>>(rel);
    cudaEventRecord(ev_prep, s_side);

    ln_kernel<<<TOK, 256>>>(x, ln_g, ln_b);
    cudaEventRecord(ev_ln, 0);

    // side: G2 -> SIM (overlaps G1 on main)
    cudaStreamWaitEvent(s_side, ev_ln, 0);
    gemm_kernel<M_G2> <<<dim3(1, 128, 1),  256, SMEM_BYTES, s_side>>>(b_qk, gam, bet);
    cudaEventRecord(ev_g2, s_side);
    gemm_kernel<M_SIM><<<dim3(2, 2, NGRP), 256, SMEM_BYTES, s_side>>>(nullptr, nullptr, nullptr);
    cudaEventRecord(ev_sim, s_side);

    // main: G1 (256x128 tiles)
    cudaStreamWaitEvent(0, ev_prep, 0);
    gemm_bf16_kernel<M_G1><<<dim3(32, 64), 256, SMEM_BF>>>(b_h, nullptr, nullptr);

    // main: LKV (needs v from G1, lkh from G2)
    cudaStreamWaitEvent(0, ev_g2, 0);
    gemm_kernel<M_LKV><<<dim3(16, 1, 16), 256, SMEM_BYTES>>>(nullptr, nullptr, nullptr);
    lkv_reduce_kernel<<<(4*QKD*HIDD)/256, 256>>>();

    // main: fused QUAD+LOUT (256-row tiles; needs attn, lkv, gate, lq)
    cudaStreamWaitEvent(0, ev_sim, 0);
    gemm_ql_kernel<<<dim3(16, 1, NGRP), 256, SMEM_QL>>>();

    // main: FIN (256x128 tiles)
    gemm_bf16_kernel<M_FIN><<<dim3(8, 64), 256, SMEM_BF>>>(b_out, x, out);
}

// round 13
// speedup vs baseline: 1.1791x; 1.1791x over previous
#include <cuda_runtime.h>
#include <cuda_bf16.h>
#include <math.h>
#include <stdint.h>

typedef __nv_bfloat16 bf16;

#define TOK   16384
#define DIMD  1024
#define HIDD  2048
#define QKD   128
#define GRP   256
#define NGRP  64
#define NPB   4096

// ---------------- device scratch ----------------
__device__ float g_normed[TOK * DIMD];              // tf32-rounded (G2 operand)
__device__ bf16  g_normedb[TOK * DIMD];             // bf16 copy (G1 operand)
__device__ bf16  g_Whb[2 * HIDD * DIMD];            // W_h transposed [n][k] bf16
__device__ bf16  g_Wob[DIMD * HIDD];                // W_out transposed [n][k] bf16
__device__ float g_Wqkr[DIMD * QKD];                // W_qk tf32-rounded
__device__ float g_v[TOK * HIDD];                   // tf32-rounded (QUAD/LKV operand)
__device__ float g_gate[TOK * HIDD];                // fp32 (output-product path!)
__device__ float g_qq[TOK * QKD];
__device__ float g_lq[TOK * QKD];
__device__ float g_qkh[TOK * QKD];
__device__ float g_lkh[TOK * QKD];
__device__ float g_bias[GRP * GRP];
__device__ float g_attn[(size_t)NGRP * GRP * GRP];
__device__ float g_lkv_part[16][QKD * HIDD];
__device__ float g_lkv[4 * QKD * HIDD];             // tf32-rounded
__device__ bf16  g_gatedb[TOK * HIDD];              // bf16 (FIN operand; measured-safe)

__device__ __forceinline__ float rna_tf32(float x) {
    float y;
    asm("cvt.rna.tf32.f32 %0, %1;\n" : "=f"(y) : "f"(x));
    return y;
}

// ---------------- small kernels ----------------

__global__ void bias_kernel(const float* __restrict__ rel_emb) {
    int idx = blockIdx.x * blockDim.x + threadIdx.x;
    int i = idx >> 8, j = idx & 255;
    int n = i - j;
    int ret = (n < 0) ? 16 : 0;
    int na = abs(n);
    int bucket;
    if (na < 8) {
        bucket = ret + na;
    } else {
        float t = logf((float)na * 0.125f) / 2.7725887298583984f;
        t = t * 8.0f;
        float r = rintf(t);
        int ti = (fabsf(t - r) < 1e-3f) ? (int)r : (int)t;
        int vl = 8 + ti;
        if (vl > 15) vl = 15;
        bucket = ret + vl;
    }
    g_bias[idx] = rel_emb[bucket] * 11.313708498984761f;
}

// 32x32 tiled transpose+convert: src f32 [K][N] -> dst bf16 [N][K]
__global__ void wtrans_kernel(const float* __restrict__ src, int which, int K, int N) {
    bf16* dst = (which == 0) ? g_Whb : g_Wob;
    __shared__ float t[32][33];
    int n0 = blockIdx.x * 32, k0 = blockIdx.y * 32;
    int tx = threadIdx.x, ty = threadIdx.y;
    #pragma unroll
    for (int i = 0; i < 4; i++)
        t[ty + 8*i][tx] = src[(size_t)(k0 + ty + 8*i) * N + n0 + tx];
    __syncthreads();
    #pragma unroll
    for (int i = 0; i < 4; i++)
        dst[(size_t)(n0 + ty + 8*i) * K + k0 + tx] = __float2bfloat16(t[tx][ty + 8*i]);
}

__global__ void wqk_round_kernel(const float* __restrict__ src) {
    int i = blockIdx.x * blockDim.x + threadIdx.x;
    g_Wqkr[i] = rna_tf32(src[i]);
}

__global__ void ln_kernel(const float* __restrict__ x,
                          const float* __restrict__ gw,
                          const float* __restrict__ bw) {
    int row = blockIdx.x;
    int t = threadIdx.x;
    const float4* xr = (const float4*)(x + (size_t)row * DIMD);
    float4 v = xr[t];
    float s  = v.x + v.y + v.z + v.w;
    float s2 = v.x*v.x + v.y*v.y + v.z*v.z + v.w*v.w;
    #pragma unroll
    for (int o = 16; o; o >>= 1) {
        s  += __shfl_xor_sync(0xffffffffu, s,  o);
        s2 += __shfl_xor_sync(0xffffffffu, s2, o);
    }
    __shared__ float sm[8], sm2[8];
    int w = t >> 5;
    if ((t & 31) == 0) { sm[w] = s; sm2[w] = s2; }
    __syncthreads();
    float ts = 0.f, ts2 = 0.f;
    #pragma unroll
    for (int k = 0; k < 8; k++) { ts += sm[k]; ts2 += sm2[k]; }
    float mu   = ts  * (1.0f / DIMD);
    float var  = ts2 * (1.0f / DIMD) - mu * mu;
    float rstd = rsqrtf(var + 1e-5f);
    float4 gv = ((const float4*)gw)[t];
    float4 bv = ((const float4*)bw)[t];
    float o0 = (v.x - mu) * rstd * gv.x + bv.x;
    float o1 = (v.y - mu) * rstd * gv.y + bv.y;
    float o2 = (v.z - mu) * rstd * gv.z + bv.z;
    float o3 = (v.w - mu) * rstd * gv.w + bv.w;
    float4 o; o.x = rna_tf32(o0); o.y = rna_tf32(o1); o.z = rna_tf32(o2); o.w = rna_tf32(o3);
    ((float4*)(g_normed + (size_t)row * DIMD))[t] = o;
    bf16* ob = g_normedb + (size_t)row * DIMD + t * 4;
    ob[0] = __float2bfloat16(o0); ob[1] = __float2bfloat16(o1);
    ob[2] = __float2bfloat16(o2); ob[3] = __float2bfloat16(o3);
}

__global__ void lkv_reduce_kernel() {
    int idx = blockIdx.x * blockDim.x + threadIdx.x;
    int b = idx >> 18;
    int r = idx & ((1 << 18) - 1);
    float s = g_lkv_part[b*4+0][r] + g_lkv_part[b*4+1][r]
            + g_lkv_part[b*4+2][r] + g_lkv_part[b*4+3][r];
    g_lkv[idx] = rna_tf32(s * (1.0f / NPB));
}

// ---------------- shared helpers ----------------

enum { M_G1 = 0, M_G2, M_SIM, M_LKV, M_FIN };

__device__ __forceinline__ float siluf(float x) { return x / (1.0f + expf(-x)); }

__device__ __forceinline__ void cpa16(void* dst, const void* src) {
    uint32_t d = (uint32_t)__cvta_generic_to_shared(dst);
    asm volatile("cp.async.cg.shared.global [%0], [%1], 16;\n" :: "r"(d), "l"(src));
}

// ---------------- TF32 GEMM (G2 / SIM / LKV): 128x128, 3-stage ----------------

template<int MODE>
__device__ __forceinline__ void epi(int r, int c, float a, int z,
                                    const float* p0, const float* p1,
                                    const float* p2) {
    if constexpr (MODE == M_G2) {
        float q = siluf(a + p0[c]);
        size_t o = (size_t)r * QKD + c;
        g_qq[o]  = rna_tf32(q * p1[0*QKD + c] + p2[0*QKD + c]);
        g_lq[o]  = rna_tf32(q * p1[1*QKD + c] + p2[1*QKD + c]);
        g_qkh[o] = rna_tf32(q * p1[2*QKD + c] + p2[2*QKD + c]);
        g_lkh[o] = rna_tf32(q * p1[3*QKD + c] + p2[3*QKD + c]);
    } else if constexpr (MODE == M_SIM) {
        float s = a * (1.0f / GRP) + g_bias[r * GRP + c];
        s = fmaxf(s, 0.0f);
        g_attn[(size_t)z * GRP * GRP + r * GRP + c] = rna_tf32(s * s);
    } else if constexpr (MODE == M_LKV) {
        g_lkv_part[z][r * HIDD + c] = a;
    }
}

#define TSTRIDE 4608
#define SMEM_T3 (6 * TSTRIDE * 4)   // 110592: 3 stages x 2 operands

template<int MODE>
__global__ void __launch_bounds__(256, 2)
gemm_kernel(const float* __restrict__ p0, const float* __restrict__ p1,
            const float* __restrict__ p2) {
    const float* A; const float* B; int K, lda, ldb;
    int z = blockIdx.z;
    if constexpr (MODE == M_G2)       { A = g_normed; B = g_Wqkr; K = DIMD; lda = DIMD; ldb = QKD; }
    else if constexpr (MODE == M_SIM) { A = g_qq  + (size_t)z*GRP*QKD; B = g_qkh + (size_t)z*GRP*QKD; K = QKD; lda = QKD; ldb = QKD; }
    else                              { int b = z >> 2, ks = z & 3;
                                        A = g_lkh + (size_t)(b*NPB + ks*1024)*QKD;
                                        B = g_v   + (size_t)(b*NPB + ks*1024)*HIDD;
                                        K = 1024; lda = QKD; ldb = HIDD; }

    constexpr bool TA = (MODE == M_LKV);   // A stored K x M  -> smem [k][m]
    constexpr bool TB = (MODE == M_SIM);   // B stored N x K  -> smem [n][k]

    extern __shared__ float smem[];
    float* Abuf = smem;
    float* Bbuf = smem + 3 * TSTRIDE;

    int tid = threadIdx.x;
    int m0 = blockIdx.y * 128, n0 = blockIdx.x * 128;
    int wid = tid >> 5, lane = tid & 31;
    int wm = (wid >> 2) * 64, wn = (wid & 3) * 32;
    int gq = lane >> 2, tg = lane & 3;

    auto load_tiles = [&](int stage, int k0) {
        float* As = Abuf + stage * TSTRIDE;
        float* Bs = Bbuf + stage * TSTRIDE;
        if constexpr (!TA) {
            #pragma unroll
            for (int r = 0; r < 4; r++) {
                int chunk = tid + r * 256;
                int row = chunk >> 3, cc = (chunk & 7) * 4;
                cpa16(&As[row * 36 + cc], A + (size_t)(m0 + row) * lda + k0 + cc);
            }
        } else {
            #pragma unroll
            for (int r = 0; r < 4; r++) {
                int chunk = tid + r * 256;
                int row = chunk >> 5, cc = (chunk & 31) * 4;
                cpa16(&As[row * 132 + cc], A + (size_t)(k0 + row) * lda + m0 + cc);
            }
        }
        if constexpr (TB) {
            #pragma unroll
            for (int r = 0; r < 4; r++) {
                int chunk = tid + r * 256;
                int row = chunk >> 3, cc = (chunk & 7) * 4;
                cpa16(&Bs[row * 36 + cc], B + (size_t)(n0 + row) * ldb + k0 + cc);
            }
        } else {
            #pragma unroll
            for (int r = 0; r < 4; r++) {
                int chunk = tid + r * 256;
                int row = chunk >> 5, cc = (chunk & 31) * 4;
                cpa16(&Bs[row * 132 + cc], B + (size_t)(k0 + row) * ldb + n0 + cc);
            }
        }
    };

    float acc[4][4][4];
    #pragma unroll
    for (int i = 0; i < 4; i++)
        #pragma unroll
        for (int j = 0; j < 4; j++)
            #pragma unroll
            for (int k = 0; k < 4; k++) acc[i][j][k] = 0.0f;

    int nK = K >> 5;
    load_tiles(0, 0);
    asm volatile("cp.async.commit_group;\n" ::);
    load_tiles(1, 32);
    asm volatile("cp.async.commit_group;\n" ::);

    for (int i = 0; i < nK; i++) {
        asm volatile("cp.async.wait_group 1;\n" ::);
        __syncthreads();
        if (i + 2 < nK) {
            load_tiles((i + 2) % 3, (i + 2) * 32);
            asm volatile("cp.async.commit_group;\n" ::);
        } else {
            asm volatile("cp.async.commit_group;\n" ::);
        }

        const float* As = Abuf + (i % 3) * TSTRIDE;
        const float* Bs = Bbuf + (i % 3) * TSTRIDE;

        #pragma unroll
        for (int ks = 0; ks < 32; ks += 8) {
            uint32_t af[4][4], bfr[4][2];
            #pragma unroll
            for (int mt = 0; mt < 4; mt++) {
                int r0 = wm + mt * 16 + gq;
                if constexpr (!TA) {
                    af[mt][0] = *(const uint32_t*)&As[(r0    ) * 36 + ks + tg];
                    af[mt][1] = *(const uint32_t*)&As[(r0 + 8) * 36 + ks + tg];
                    af[mt][2] = *(const uint32_t*)&As[(r0    ) * 36 + ks + tg + 4];
                    af[mt][3] = *(const uint32_t*)&As[(r0 + 8) * 36 + ks + tg + 4];
                } else {
                    af[mt][0] = *(const uint32_t*)&As[(ks + tg    ) * 132 + r0];
                    af[mt][1] = *(const uint32_t*)&As[(ks + tg    ) * 132 + r0 + 8];
                    af[mt][2] = *(const uint32_t*)&As[(ks + tg + 4) * 132 + r0];
                    af[mt][3] = *(const uint32_t*)&As[(ks + tg + 4) * 132 + r0 + 8];
                }
            }
            #pragma unroll
            for (int nt = 0; nt < 4; nt++) {
                int c0 = wn + nt * 8 + gq;
                if constexpr (TB) {
                    bfr[nt][0] = *(const uint32_t*)&Bs[c0 * 36 + ks + tg];
                    bfr[nt][1] = *(const uint32_t*)&Bs[c0 * 36 + ks + tg + 4];
                } else {
                    bfr[nt][0] = *(const uint32_t*)&Bs[(ks + tg    ) * 132 + c0];
                    bfr[nt][1] = *(const uint32_t*)&Bs[(ks + tg + 4) * 132 + c0];
                }
            }
            #pragma unroll
            for (int mt = 0; mt < 4; mt++)
                #pragma unroll
                for (int nt = 0; nt < 4; nt++) {
                    asm volatile(
                        "mma.sync.aligned.m16n8k8.row.col.f32.tf32.tf32.f32 "
                        "{%0,%1,%2,%3},{%4,%5,%6,%7},{%8,%9},{%0,%1,%2,%3};\n"
                        : "+f"(acc[mt][nt][0]), "+f"(acc[mt][nt][1]),
                          "+f"(acc[mt][nt][2]), "+f"(acc[mt][nt][3])
                        : "r"(af[mt][0]), "r"(af[mt][1]), "r"(af[mt][2]), "r"(af[mt][3]),
                          "r"(bfr[nt][0]), "r"(bfr[nt][1]));
                }
        }
    }

    #pragma unroll
    for (int mt = 0; mt < 4; mt++)
        #pragma unroll
        for (int nt = 0; nt < 4; nt++) {
            int r0 = m0 + wm + mt * 16 + gq;
            int c0 = n0 + wn + nt * 8 + tg * 2;
            epi<MODE>(r0,     c0,     acc[mt][nt][0], z, p0, p1, p2);
            epi<MODE>(r0,     c0 + 1, acc[mt][nt][1], z, p0, p1, p2);
            epi<MODE>(r0 + 8, c0,     acc[mt][nt][2], z, p0, p1, p2);
            epi<MODE>(r0 + 8, c0 + 1, acc[mt][nt][3], z, p0, p1, p2);
        }
}

// ---------- fused QUAD+LOUT (tf32): 128x128, 3-stage ----------

__global__ void __launch_bounds__(256, 2)
gemm_ql_kernel() {
    int z = blockIdx.z;          // group 0..63
    int b = z >> 4;              // batch
    const float* A1 = g_attn + (size_t)z * GRP * GRP;   // [m][k], lda GRP
    const float* B1 = g_v    + (size_t)z * GRP * HIDD;  // [k][n], ldb HIDD
    const float* A2 = g_lq   + (size_t)z * GRP * QKD;   // [m][k], lda QKD
    const float* B2 = g_lkv  + (size_t)b * QKD * HIDD;  // [k][n], ldb HIDD

    extern __shared__ float smem[];
    float* Abuf = smem;
    float* Bbuf = smem + 3 * TSTRIDE;

    int tid = threadIdx.x;
    int m0 = blockIdx.y * 128, n0 = blockIdx.x * 128;
    int wid = tid >> 5, lane = tid & 31;
    int wm = (wid >> 2) * 64, wn = (wid & 3) * 32;
    int gq = lane >> 2, tg = lane & 3;

    auto load_tiles = [&](int stage, int slab) {
        float* As = Abuf + stage * TSTRIDE;
        float* Bs = Bbuf + stage * TSTRIDE;
        const float* A; const float* B; int lda, k0;
        if (slab < 8) { A = A1; lda = GRP; k0 = slab * 32; B = B1 + (size_t)k0 * HIDD; }
        else          { A = A2; lda = QKD; k0 = (slab - 8) * 32; B = B2 + (size_t)k0 * HIDD; }
        #pragma unroll
        for (int r = 0; r < 4; r++) {
            int chunk = tid + r * 256;
            int row = chunk >> 3, cc = (chunk & 7) * 4;
            cpa16(&As[row * 36 + cc], A + (size_t)(m0 + row) * lda + k0 + cc);
        }
        #pragma unroll
        for (int r = 0; r < 4; r++) {
            int chunk = tid + r * 256;
            int row = chunk >> 5, cc = (chunk & 31) * 4;
            cpa16(&Bs[row * 132 + cc], B + (size_t)row * HIDD + n0 + cc);
        }
    };

    float acc[4][4][4];
    #pragma unroll
    for (int i = 0; i < 4; i++)
        #pragma unroll
        for (int j = 0; j < 4; j++)
            #pragma unroll
            for (int k = 0; k < 4; k++) acc[i][j][k] = 0.0f;

    const int nSlab = 12;        // 8 (attn@v) + 4 (lq@lkv)
    load_tiles(0, 0);
    asm volatile("cp.async.commit_group;\n" ::);
    load_tiles(1, 1);
    asm volatile("cp.async.commit_group;\n" ::);

    for (int i = 0; i < nSlab; i++) {
        asm volatile("cp.async.wait_group 1;\n" ::);
        __syncthreads();
        if (i + 2 < nSlab) {
            load_tiles((i + 2) % 3, i + 2);
            asm volatile("cp.async.commit_group;\n" ::);
        } else {
            asm volatile("cp.async.commit_group;\n" ::);
        }

        const float* As = Abuf + (i % 3) * TSTRIDE;
        const float* Bs = Bbuf + (i % 3) * TSTRIDE;

        #pragma unroll
        for (int ks = 0; ks < 32; ks += 8) {
            uint32_t af[4][4], bfr[4][2];
            #pragma unroll
            for (int mt = 0; mt < 4; mt++) {
                int r0 = wm + mt * 16 + gq;
                af[mt][0] = *(const uint32_t*)&As[(r0    ) * 36 + ks + tg];
                af[mt][1] = *(const uint32_t*)&As[(r0 + 8) * 36 + ks + tg];
                af[mt][2] = *(const uint32_t*)&As[(r0    ) * 36 + ks + tg + 4];
                af[mt][3] = *(const uint32_t*)&As[(r0 + 8) * 36 + ks + tg + 4];
            }
            #pragma unroll
            for (int nt = 0; nt < 4; nt++) {
                int c0 = wn + nt * 8 + gq;
                bfr[nt][0] = *(const uint32_t*)&Bs[(ks + tg    ) * 132 + c0];
                bfr[nt][1] = *(const uint32_t*)&Bs[(ks + tg + 4) * 132 + c0];
            }
            #pragma unroll
            for (int mt = 0; mt < 4; mt++)
                #pragma unroll
                for (int nt = 0; nt < 4; nt++) {
                    asm volatile(
                        "mma.sync.aligned.m16n8k8.row.col.f32.tf32.tf32.f32 "
                        "{%0,%1,%2,%3},{%4,%5,%6,%7},{%8,%9},{%0,%1,%2,%3};\n"
                        : "+f"(acc[mt][nt][0]), "+f"(acc[mt][nt][1]),
                          "+f"(acc[mt][nt][2]), "+f"(acc[mt][nt][3])
                        : "r"(af[mt][0]), "r"(af[mt][1]), "r"(af[mt][2]), "r"(af[mt][3]),
                          "r"(bfr[nt][0]), "r"(bfr[nt][1]));
                }
        }
    }

    #pragma unroll
    for (int mt = 0; mt < 4; mt++)
        #pragma unroll
        for (int nt = 0; nt < 4; nt++) {
            int r0 = m0 + wm + mt * 16 + gq;     // row within group (0..255)
            int c0 = n0 + wn + nt * 8 + tg * 2;
            #pragma unroll
            for (int e = 0; e < 4; e++) {
                int r = r0 + (e >> 1) * 8;
                int c = c0 + (e & 1);
                size_t o = ((size_t)z * GRP + r) * HIDD + c;
                g_gatedb[o] = __float2bfloat16(g_gate[o] * acc[mt][nt][e]);
            }
        }
}

// ---------- BF16 GEMM (G1, FIN): 128x128, 3-stage + ldmatrix (R8 proven) ----------

#define HSTRIDE 5120   // bf16 elems per stage per operand (128*40)
#define SMEM_BF (6 * HSTRIDE * 2)   // 61440

template<int MODE>
__global__ void __launch_bounds__(256, 2)
gemm_bf16_kernel(const float* __restrict__ p0, const float* __restrict__ p2,
                 float* __restrict__ pf) {
    const bf16* A; const bf16* B; int K;
    if constexpr (MODE == M_G1) { A = g_normedb; B = g_Whb; K = DIMD; }
    else                        { A = g_gatedb;  B = g_Wob; K = HIDD; }

    extern __shared__ bf16 hsm[];
    bf16* Abuf = hsm;
    bf16* Bbuf = hsm + 3 * HSTRIDE;

    int tid = threadIdx.x;
    int m0 = blockIdx.y * 128, n0 = blockIdx.x * 128;
    int wid = tid >> 5, lane = tid & 31;
    int wm = (wid >> 2) * 64, wn = (wid & 3) * 32;
    int gq = lane >> 2, tg = lane & 3;
    int lrow = lane & 7, lmat = lane >> 3;

    auto load_tiles = [&](int stage, int k0) {
        bf16* As = Abuf + stage * HSTRIDE;
        bf16* Bs = Bbuf + stage * HSTRIDE;
        #pragma unroll
        for (int r = 0; r < 2; r++) {
            int chunk = tid + r * 256;
            int row = chunk >> 2, cc = (chunk & 3) * 8;
            cpa16(&As[row * 40 + cc], A + (size_t)(m0 + row) * K + k0 + cc);
        }
        #pragma unroll
        for (int r = 0; r < 2; r++) {
            int chunk = tid + r * 256;
            int row = chunk >> 2, cc = (chunk & 3) * 8;
            cpa16(&Bs[row * 40 + cc], B + (size_t)(n0 + row) * K + k0 + cc);
        }
    };

    float acc[4][4][4];
    #pragma unroll
    for (int i = 0; i < 4; i++)
        #pragma unroll
        for (int j = 0; j < 4; j++)
            #pragma unroll
            for (int k = 0; k < 4; k++) acc[i][j][k] = 0.0f;

    int nK = K >> 5;
    load_tiles(0, 0);
    asm volatile("cp.async.commit_group;\n" ::);
    load_tiles(1, 32);
    asm volatile("cp.async.commit_group;\n" ::);

    for (int i = 0; i < nK; i++) {
        asm volatile("cp.async.wait_group 1;\n" ::);
        __syncthreads();
        if (i + 2 < nK) {
            load_tiles((i + 2) % 3, (i + 2) * 32);
            asm volatile("cp.async.commit_group;\n" ::);
        } else {
            asm volatile("cp.async.commit_group;\n" ::);
        }

        const bf16* As = Abuf + (i % 3) * HSTRIDE;
        const bf16* Bs = Bbuf + (i % 3) * HSTRIDE;

        #pragma unroll
        for (int ks = 0; ks < 32; ks += 16) {
            uint32_t af[4][4], bfr[4][2];
            #pragma unroll
            for (int mt = 0; mt < 4; mt++) {
                const bf16* p = &As[(size_t)(wm + mt * 16 + lrow + (lmat & 1) * 8) * 40
                                    + ks + (lmat >> 1) * 8];
                uint32_t addr = (uint32_t)__cvta_generic_to_shared(p);
                asm volatile(
                    "ldmatrix.sync.aligned.m8n8.x4.shared.b16 {%0,%1,%2,%3}, [%4];\n"
                    : "=r"(af[mt][0]), "=r"(af[mt][1]), "=r"(af[mt][2]), "=r"(af[mt][3])
                    : "r"(addr));
            }
            #pragma unroll
            for (int np = 0; np < 2; np++) {
                const bf16* p = &Bs[(size_t)(wn + np * 16 + lrow + (lmat >> 1) * 8) * 40
                                    + ks + (lmat & 1) * 8];
                uint32_t addr = (uint32_t)__cvta_generic_to_shared(p);
                asm volatile(
                    "ldmatrix.sync.aligned.m8n8.x4.shared.b16 {%0,%1,%2,%3}, [%4];\n"
                    : "=r"(bfr[2*np][0]), "=r"(bfr[2*np][1]),
                      "=r"(bfr[2*np+1][0]), "=r"(bfr[2*np+1][1])
                    : "r"(addr));
            }
            #pragma unroll
            for (int mt = 0; mt < 4; mt++)
                #pragma unroll
                for (int nt = 0; nt < 4; nt++) {
                    asm volatile(
                        "mma.sync.aligned.m16n8k16.row.col.f32.bf16.bf16.f32 "
                        "{%0,%1,%2,%3},{%4,%5,%6,%7},{%8,%9},{%0,%1,%2,%3};\n"
                        : "+f"(acc[mt][nt][0]), "+f"(acc[mt][nt][1]),
                          "+f"(acc[mt][nt][2]), "+f"(acc[mt][nt][3])
                        : "r"(af[mt][0]), "r"(af[mt][1]), "r"(af[mt][2]), "r"(af[mt][3]),
                          "r"(bfr[nt][0]), "r"(bfr[nt][1]));
                }
        }
    }

    #pragma unroll
    for (int mt = 0; mt < 4; mt++)
        #pragma unroll
        for (int nt = 0; nt < 4; nt++) {
            int r0 = m0 + wm + mt * 16 + gq;
            int c0 = n0 + wn + nt * 8 + tg * 2;
            #pragma unroll
            for (int e = 0; e < 4; e++) {
                int r = r0 + (e >> 1) * 8;
                int c = c0 + (e & 1);
                float a = acc[mt][nt][e];
                if constexpr (MODE == M_G1) {
                    float h = siluf(a + p0[c]);
                    if (c < HIDD) g_v[(size_t)r * HIDD + c] = rna_tf32(h);
                    else          g_gate[(size_t)r * HIDD + (c - HIDD)] = h;
                } else {
                    size_t o = (size_t)r * DIMD + c;
                    pf[o] = a + p0[c] + p2[o];
                }
            }
        }
}

// ---------------- launch ----------------

extern "C" void kernel_launch(void* const* d_in, const int* in_sizes, int n_in,
                              void* d_out, int out_size) {
    const float* x     = (const float*)d_in[0];
    const float* ln_g  = (const float*)d_in[1];
    const float* ln_b  = (const float*)d_in[2];
    const float* W_h   = (const float*)d_in[3];
    const float* b_h   = (const float*)d_in[4];
    const float* W_qk  = (const float*)d_in[5];
    const float* b_qk  = (const float*)d_in[6];
    const float* gam   = (const float*)d_in[7];
    const float* bet   = (const float*)d_in[8];
    const float* rel   = (const float*)d_in[9];
    const float* W_out = (const float*)d_in[10];
    const float* b_out = (const float*)d_in[11];
    float* out = (float*)d_out;

    (void)in_sizes; (void)n_in; (void)out_size;

    static cudaStream_t s_side = nullptr;
    static cudaEvent_t ev_fork = nullptr, ev_prep = nullptr, ev_ln = nullptr,
                       ev_g2 = nullptr, ev_sim = nullptr;
    if (!s_side) {
        cudaStreamCreateWithFlags(&s_side, cudaStreamNonBlocking);
        cudaEventCreateWithFlags(&ev_fork, cudaEventDisableTiming);
        cudaEventCreateWithFlags(&ev_prep, cudaEventDisableTiming);
        cudaEventCreateWithFlags(&ev_ln,   cudaEventDisableTiming);
        cudaEventCreateWithFlags(&ev_g2,   cudaEventDisableTiming);
        cudaEventCreateWithFlags(&ev_sim,  cudaEventDisableTiming);
        cudaFuncSetAttribute(gemm_kernel<M_G2>,  cudaFuncAttributeMaxDynamicSharedMemorySize, SMEM_T3);
        cudaFuncSetAttribute(gemm_kernel<M_SIM>, cudaFuncAttributeMaxDynamicSharedMemorySize, SMEM_T3);
        cudaFuncSetAttribute(gemm_kernel<M_LKV>, cudaFuncAttributeMaxDynamicSharedMemorySize, SMEM_T3);
        cudaFuncSetAttribute(gemm_ql_kernel,     cudaFuncAttributeMaxDynamicSharedMemorySize, SMEM_T3);
        cudaFuncSetAttribute(gemm_bf16_kernel<M_G1>, cudaFuncAttributeMaxDynamicSharedMemorySize, SMEM_BF);
        cudaFuncSetAttribute(gemm_bf16_kernel<M_FIN>,cudaFuncAttributeMaxDynamicSharedMemorySize, SMEM_BF);
    }

    // fork; prep on side while ln runs on main
    cudaEventRecord(ev_fork, 0);
    cudaStreamWaitEvent(s_side, ev_fork, 0);

    wtrans_kernel<<<dim3(128, 32), dim3(32, 8), 0, s_side>>>(W_h, 0, DIMD, 2*HIDD);
    wtrans_kernel<<<dim3(32, 64),  dim3(32, 8), 0, s_side>>>(W_out, 1, HIDD, DIMD);
    wqk_round_kernel<<<(DIMD*QKD)/256, 256, 0, s_side>>>(W_qk);
    bias_kernel<<<(GRP*GRP)/256, 256, 0, s_side>>>(rel);
    cudaEventRecord(ev_prep, s_side);

    ln_kernel<<<TOK, 256>>>(x, ln_g, ln_b);
    cudaEventRecord(ev_ln, 0);

    // side: G2 -> SIM (overlaps G1 on main)
    cudaStreamWaitEvent(s_side, ev_ln, 0);
    gemm_kernel<M_G2> <<<dim3(1, 128, 1),  256, SMEM_T3, s_side>>>(b_qk, gam, bet);
    cudaEventRecord(ev_g2, s_side);
    gemm_kernel<M_SIM><<<dim3(2, 2, NGRP), 256, SMEM_T3, s_side>>>(nullptr, nullptr, nullptr);
    cudaEventRecord(ev_sim, s_side);

    // main: G1 (128x128, 2 CTA/SM)
    cudaStreamWaitEvent(0, ev_prep, 0);
    gemm_bf16_kernel<M_G1><<<dim3(32, 128), 256, SMEM_BF>>>(b_h, nullptr, nullptr);

    // main: LKV (needs v from G1, lkh from G2)
    cudaStreamWaitEvent(0, ev_g2, 0);
    gemm_kernel<M_LKV><<<dim3(16, 1, 16), 256, SMEM_T3>>>(nullptr, nullptr, nullptr);
    lkv_reduce_kernel<<<(4*QKD*HIDD)/256, 256>>>();

    // main: fused QUAD+LOUT (needs attn, lkv, gate, lq)
    cudaStreamWaitEvent(0, ev_sim, 0);
    gemm_ql_kernel<<<dim3(16, 2, NGRP), 256, SMEM_T3>>>();

    // main: FIN
    gemm_bf16_kernel<M_FIN><<<dim3(8, 128), 256, SMEM_BF>>>(b_out, x, out);
}

// round 14
// speedup vs baseline: 1.3134x; 1.1139x over previous
#include <cuda_runtime.h>
#include <cuda_bf16.h>
#include <math.h>
#include <stdint.h>

typedef __nv_bfloat16 bf16;

#define TOK   16384
#define DIMD  1024
#define HIDD  2048
#define QKD   128
#define GRP   256
#define NGRP  64
#define NPB   4096

// ---------------- device scratch ----------------
__device__ float g_normed[TOK * DIMD];              // tf32-rounded (G2 operand)
__device__ bf16  g_normedb[TOK * DIMD];             // bf16 copy (G1 operand)
__device__ bf16  g_Whb[2 * HIDD * DIMD];            // W_h transposed [n][k] bf16
__device__ bf16  g_Wob[DIMD * HIDD];                // W_out transposed [n][k] bf16
__device__ float g_Wqkr[DIMD * QKD];                // W_qk tf32-rounded
__device__ bf16  g_vb[TOK * HIDD];                  // bf16 (QL/LKV B operand)
__device__ float g_gate[TOK * HIDD];                // fp32 (output-product path!)
__device__ float g_qq[TOK * QKD];                   // tf32 (SIM operand - precision critical)
__device__ bf16  g_lqb[TOK * QKD];                  // bf16 (QL lin operand)
__device__ float g_qkh[TOK * QKD];                  // tf32 (SIM operand - precision critical)
__device__ bf16  g_lkhb[TOK * QKD];                 // bf16 (LKV operand)
__device__ float g_bias[GRP * GRP];
__device__ bf16  g_attnb[(size_t)NGRP * GRP * GRP]; // bf16 (QL quad operand)
__device__ float g_lkv_part[16][QKD * HIDD];        // fp32 partials
__device__ bf16  g_lkvb[4 * QKD * HIDD];            // bf16 (QL lin B operand)
__device__ bf16  g_gatedb[TOK * HIDD];              // bf16 (FIN operand)

__device__ __forceinline__ float rna_tf32(float x) {
    float y;
    asm("cvt.rna.tf32.f32 %0, %1;\n" : "=f"(y) : "f"(x));
    return y;
}

// ---------------- small kernels ----------------

__global__ void bias_kernel(const float* __restrict__ rel_emb) {
    int idx = blockIdx.x * blockDim.x + threadIdx.x;
    int i = idx >> 8, j = idx & 255;
    int n = i - j;
    int ret = (n < 0) ? 16 : 0;
    int na = abs(n);
    int bucket;
    if (na < 8) {
        bucket = ret + na;
    } else {
        float t = logf((float)na * 0.125f) / 2.7725887298583984f;
        t = t * 8.0f;
        float r = rintf(t);
        int ti = (fabsf(t - r) < 1e-3f) ? (int)r : (int)t;
        int vl = 8 + ti;
        if (vl > 15) vl = 15;
        bucket = ret + vl;
    }
    g_bias[idx] = rel_emb[bucket] * 11.313708498984761f;
}

// 32x32 tiled transpose+convert: src f32 [K][N] -> dst bf16 [N][K]
__global__ void wtrans_kernel(const float* __restrict__ src, int which, int K, int N) {
    bf16* dst = (which == 0) ? g_Whb : g_Wob;
    __shared__ float t[32][33];
    int n0 = blockIdx.x * 32, k0 = blockIdx.y * 32;
    int tx = threadIdx.x, ty = threadIdx.y;
    #pragma unroll
    for (int i = 0; i < 4; i++)
        t[ty + 8*i][tx] = src[(size_t)(k0 + ty + 8*i) * N + n0 + tx];
    __syncthreads();
    #pragma unroll
    for (int i = 0; i < 4; i++)
        dst[(size_t)(n0 + ty + 8*i) * K + k0 + tx] = __float2bfloat16(t[tx][ty + 8*i]);
}

__global__ void wqk_round_kernel(const float* __restrict__ src) {
    int i = blockIdx.x * blockDim.x + threadIdx.x;
    g_Wqkr[i] = rna_tf32(src[i]);
}

__global__ void ln_kernel(const float* __restrict__ x,
                          const float* __restrict__ gw,
                          const float* __restrict__ bw) {
    int row = blockIdx.x;
    int t = threadIdx.x;
    const float4* xr = (const float4*)(x + (size_t)row * DIMD);
    float4 v = xr[t];
    float s  = v.x + v.y + v.z + v.w;
    float s2 = v.x*v.x + v.y*v.y + v.z*v.z + v.w*v.w;
    #pragma unroll
    for (int o = 16; o; o >>= 1) {
        s  += __shfl_xor_sync(0xffffffffu, s,  o);
        s2 += __shfl_xor_sync(0xffffffffu, s2, o);
    }
    __shared__ float sm[8], sm2[8];
    int w = t >> 5;
    if ((t & 31) == 0) { sm[w] = s; sm2[w] = s2; }
    __syncthreads();
    float ts = 0.f, ts2 = 0.f;
    #pragma unroll
    for (int k = 0; k < 8; k++) { ts += sm[k]; ts2 += sm2[k]; }
    float mu   = ts  * (1.0f / DIMD);
    float var  = ts2 * (1.0f / DIMD) - mu * mu;
    float rstd = rsqrtf(var + 1e-5f);
    float4 gv = ((const float4*)gw)[t];
    float4 bv = ((const float4*)bw)[t];
    float o0 = (v.x - mu) * rstd * gv.x + bv.x;
    float o1 = (v.y - mu) * rstd * gv.y + bv.y;
    float o2 = (v.z - mu) * rstd * gv.z + bv.z;
    float o3 = (v.w - mu) * rstd * gv.w + bv.w;
    float4 o; o.x = rna_tf32(o0); o.y = rna_tf32(o1); o.z = rna_tf32(o2); o.w = rna_tf32(o3);
    ((float4*)(g_normed + (size_t)row * DIMD))[t] = o;
    bf16* ob = g_normedb + (size_t)row * DIMD + t * 4;
    ob[0] = __float2bfloat16(o0); ob[1] = __float2bfloat16(o1);
    ob[2] = __float2bfloat16(o2); ob[3] = __float2bfloat16(o3);
}

__global__ void lkv_reduce_kernel() {
    int idx = blockIdx.x * blockDim.x + threadIdx.x;
    int b = idx >> 18;
    int r = idx & ((1 << 18) - 1);
    float s = g_lkv_part[b*4+0][r] + g_lkv_part[b*4+1][r]
            + g_lkv_part[b*4+2][r] + g_lkv_part[b*4+3][r];
    g_lkvb[idx] = __float2bfloat16(s * (1.0f / NPB));
}

// ---------------- shared helpers ----------------

enum { M_G1 = 0, M_G2, M_SIM, M_FIN };

__device__ __forceinline__ float siluf(float x) { return x / (1.0f + expf(-x)); }

__device__ __forceinline__ void cpa16(void* dst, const void* src) {
    uint32_t d = (uint32_t)__cvta_generic_to_shared(dst);
    asm volatile("cp.async.cg.shared.global [%0], [%1], 16;\n" :: "r"(d), "l"(src));
}

// ---------------- TF32 GEMM (G2 / SIM): 128x128, 3-stage ----------------

template<int MODE>
__device__ __forceinline__ void epi(int r, int c, float a, int z,
                                    const float* p0, const float* p1,
                                    const float* p2) {
    if constexpr (MODE == M_G2) {
        float q = siluf(a + p0[c]);
        size_t o = (size_t)r * QKD + c;
        g_qq[o]   = rna_tf32(q * p1[0*QKD + c] + p2[0*QKD + c]);
        g_lqb[o]  = __float2bfloat16(q * p1[1*QKD + c] + p2[1*QKD + c]);
        g_qkh[o]  = rna_tf32(q * p1[2*QKD + c] + p2[2*QKD + c]);
        g_lkhb[o] = __float2bfloat16(q * p1[3*QKD + c] + p2[3*QKD + c]);
    } else if constexpr (MODE == M_SIM) {
        float s = a * (1.0f / GRP) + g_bias[r * GRP + c];
        s = fmaxf(s, 0.0f);
        g_attnb[(size_t)z * GRP * GRP + r * GRP + c] = __float2bfloat16(s * s);
    }
}

#define TSTRIDE 4608
#define SMEM_T3 (6 * TSTRIDE * 4)   // 110592: 3 stages x 2 operands

template<int MODE>
__global__ void __launch_bounds__(256, 2)
gemm_kernel(const float* __restrict__ p0, const float* __restrict__ p1,
            const float* __restrict__ p2) {
    const float* A; const float* B; int K, lda, ldb;
    int z = blockIdx.z;
    if constexpr (MODE == M_G2) { A = g_normed; B = g_Wqkr; K = DIMD; lda = DIMD; ldb = QKD; }
    else                        { A = g_qq  + (size_t)z*GRP*QKD; B = g_qkh + (size_t)z*GRP*QKD; K = QKD; lda = QKD; ldb = QKD; }

    constexpr bool TB = (MODE == M_SIM);   // B stored N x K  -> smem [n][k]

    extern __shared__ float smem[];
    float* Abuf = smem;
    float* Bbuf = smem + 3 * TSTRIDE;

    int tid = threadIdx.x;
    int m0 = blockIdx.y * 128, n0 = blockIdx.x * 128;
    int wid = tid >> 5, lane = tid & 31;
    int wm = (wid >> 2) * 64, wn = (wid & 3) * 32;
    int gq = lane >> 2, tg = lane & 3;

    auto load_tiles = [&](int stage, int k0) {
        float* As = Abuf + stage * TSTRIDE;
        float* Bs = Bbuf + stage * TSTRIDE;
        #pragma unroll
        for (int r = 0; r < 4; r++) {
            int chunk = tid + r * 256;
            int row = chunk >> 3, cc = (chunk & 7) * 4;
            cpa16(&As[row * 36 + cc], A + (size_t)(m0 + row) * lda + k0 + cc);
        }
        if constexpr (TB) {
            #pragma unroll
            for (int r = 0; r < 4; r++) {
                int chunk = tid + r * 256;
                int row = chunk >> 3, cc = (chunk & 7) * 4;
                cpa16(&Bs[row * 36 + cc], B + (size_t)(n0 + row) * ldb + k0 + cc);
            }
        } else {
            #pragma unroll
            for (int r = 0; r < 4; r++) {
                int chunk = tid + r * 256;
                int row = chunk >> 5, cc = (chunk & 31) * 4;
                cpa16(&Bs[row * 132 + cc], B + (size_t)(k0 + row) * ldb + n0 + cc);
            }
        }
    };

    float acc[4][4][4];
    #pragma unroll
    for (int i = 0; i < 4; i++)
        #pragma unroll
        for (int j = 0; j < 4; j++)
            #pragma unroll
            for (int k = 0; k < 4; k++) acc[i][j][k] = 0.0f;

    int nK = K >> 5;
    load_tiles(0, 0);
    asm volatile("cp.async.commit_group;\n" ::);
    load_tiles(1, 32);
    asm volatile("cp.async.commit_group;\n" ::);

    for (int i = 0; i < nK; i++) {
        asm volatile("cp.async.wait_group 1;\n" ::);
        __syncthreads();
        if (i + 2 < nK) {
            load_tiles((i + 2) % 3, (i + 2) * 32);
            asm volatile("cp.async.commit_group;\n" ::);
        } else {
            asm volatile("cp.async.commit_group;\n" ::);
        }

        const float* As = Abuf + (i % 3) * TSTRIDE;
        const float* Bs = Bbuf + (i % 3) * TSTRIDE;

        #pragma unroll
        for (int ks = 0; ks < 32; ks += 8) {
            uint32_t af[4][4], bfr[4][2];
            #pragma unroll
            for (int mt = 0; mt < 4; mt++) {
                int r0 = wm + mt * 16 + gq;
                af[mt][0] = *(const uint32_t*)&As[(r0    ) * 36 + ks + tg];
                af[mt][1] = *(const uint32_t*)&As[(r0 + 8) * 36 + ks + tg];
                af[mt][2] = *(const uint32_t*)&As[(r0    ) * 36 + ks + tg + 4];
                af[mt][3] = *(const uint32_t*)&As[(r0 + 8) * 36 + ks + tg + 4];
            }
            #pragma unroll
            for (int nt = 0; nt < 4; nt++) {
                int c0 = wn + nt * 8 + gq;
                if constexpr (TB) {
                    bfr[nt][0] = *(const uint32_t*)&Bs[c0 * 36 + ks + tg];
                    bfr[nt][1] = *(const uint32_t*)&Bs[c0 * 36 + ks + tg + 4];
                } else {
                    bfr[nt][0] = *(const uint32_t*)&Bs[(ks + tg    ) * 132 + c0];
                    bfr[nt][1] = *(const uint32_t*)&Bs[(ks + tg + 4) * 132 + c0];
                }
            }
            #pragma unroll
            for (int mt = 0; mt < 4; mt++)
                #pragma unroll
                for (int nt = 0; nt < 4; nt++) {
                    asm volatile(
                        "mma.sync.aligned.m16n8k8.row.col.f32.tf32.tf32.f32 "
                        "{%0,%1,%2,%3},{%4,%5,%6,%7},{%8,%9},{%0,%1,%2,%3};\n"
                        : "+f"(acc[mt][nt][0]), "+f"(acc[mt][nt][1]),
                          "+f"(acc[mt][nt][2]), "+f"(acc[mt][nt][3])
                        : "r"(af[mt][0]), "r"(af[mt][1]), "r"(af[mt][2]), "r"(af[mt][3]),
                          "r"(bfr[nt][0]), "r"(bfr[nt][1]));
                }
        }
    }

    #pragma unroll
    for (int mt = 0; mt < 4; mt++)
        #pragma unroll
        for (int nt = 0; nt < 4; nt++) {
            int r0 = m0 + wm + mt * 16 + gq;
            int c0 = n0 + wn + nt * 8 + tg * 2;
            epi<MODE>(r0,     c0,     acc[mt][nt][0], z, p0, p1, p2);
            epi<MODE>(r0,     c0 + 1, acc[mt][nt][1], z, p0, p1, p2);
            epi<MODE>(r0 + 8, c0,     acc[mt][nt][2], z, p0, p1, p2);
            epi<MODE>(r0 + 8, c0 + 1, acc[mt][nt][3], z, p0, p1, p2);
        }
}

// ---------- LKV (bf16): lin_kv partials, A=[k][m] + B=[k][n] via ldmatrix.trans ----------

#define LSTR 136                      // bf16 row stride for [k][*] tiles
#define LSTG (32 * LSTR)              // 4352 bf16 per operand-stage
#define SMEM_LKV (LSTG * 2 * 3 * 2)   // 52224 bytes

__global__ void __launch_bounds__(256, 2)
gemm_lkv_kernel() {
    int z = blockIdx.z;
    int b = z >> 2, kspl = z & 3;
    const bf16* A = g_lkhb + (size_t)(b*NPB + kspl*1024)*QKD;   // [k][m] (token x qk)
    const bf16* B = g_vb   + (size_t)(b*NPB + kspl*1024)*HIDD;  // [k][n] (token x hid)
    int n0 = blockIdx.x * 128;

    extern __shared__ bf16 hsm[];
    bf16* Abuf = hsm;
    bf16* Bbuf = hsm + 3 * LSTG;

    int tid = threadIdx.x;
    int wid = tid >> 5, lane = tid & 31;
    int wm = (wid >> 2) * 64, wn = (wid & 3) * 32;
    int gq = lane >> 2, tg = lane & 3;
    int lrow = lane & 7, lmat = lane >> 3;

    auto load_tiles = [&](int stage, int k0) {
        bf16* As = Abuf + stage * LSTG;
        bf16* Bs = Bbuf + stage * LSTG;
        #pragma unroll
        for (int r = 0; r < 2; r++) {             // A: 32 k-rows x 16 chunks
            int chunk = tid + r * 256;
            int row = chunk >> 4, cc = (chunk & 15) * 8;
            cpa16(&As[row * LSTR + cc], A + (size_t)(k0 + row) * QKD + cc);
        }
        #pragma unroll
        for (int r = 0; r < 2; r++) {             // B: 32 k-rows x 16 chunks
            int chunk = tid + r * 256;
            int row = chunk >> 4, cc = (chunk & 15) * 8;
            cpa16(&Bs[row * LSTR + cc], B + (size_t)(k0 + row) * HIDD + n0 + cc);
        }
    };

    float acc[4][4][4];
    #pragma unroll
    for (int i = 0; i < 4; i++)
        #pragma unroll
        for (int j = 0; j < 4; j++)
            #pragma unroll
            for (int k = 0; k < 4; k++) acc[i][j][k] = 0.0f;

    const int nK = 32;                 // 1024 / 32
    load_tiles(0, 0);
    asm volatile("cp.async.commit_group;\n" ::);
    load_tiles(1, 32);
    asm volatile("cp.async.commit_group;\n" ::);

    for (int i = 0; i < nK; i++) {
        asm volatile("cp.async.wait_group 1;\n" ::);
        __syncthreads();
        if (i + 2 < nK) {
            load_tiles((i + 2) % 3, (i + 2) * 32);
            asm volatile("cp.async.commit_group;\n" ::);
        } else {
            asm volatile("cp.async.commit_group;\n" ::);
        }

        const bf16* As = Abuf + (i % 3) * LSTG;
        const bf16* Bs = Bbuf + (i % 3) * LSTG;

        #pragma unroll
        for (int ks = 0; ks < 32; ks += 16) {
            uint32_t af[4][4], bfr[4][2];
            #pragma unroll
            for (int mt = 0; mt < 4; mt++) {      // A: trans ([k][m] source)
                const bf16* p = &As[(size_t)(ks + (lmat >> 1) * 8 + lrow) * LSTR
                                    + wm + mt * 16 + (lmat & 1) * 8];
                uint32_t addr = (uint32_t)__cvta_generic_to_shared(p);
                asm volatile(
                    "ldmatrix.sync.aligned.m8n8.x4.trans.shared.b16 {%0,%1,%2,%3}, [%4];\n"
                    : "=r"(af[mt][0]), "=r"(af[mt][1]), "=r"(af[mt][2]), "=r"(af[mt][3])
                    : "r"(addr));
            }
            #pragma unroll
            for (int np = 0; np < 2; np++) {      // B: trans ([k][n] source)
                const bf16* p = &Bs[(size_t)(ks + (lmat & 1) * 8 + lrow) * LSTR
                                    + wn + np * 16 + (lmat >> 1) * 8];
                uint32_t addr = (uint32_t)__cvta_generic_to_shared(p);
                asm volatile(
                    "ldmatrix.sync.aligned.m8n8.x4.trans.shared.b16 {%0,%1,%2,%3}, [%4];\n"
                    : "=r"(bfr[2*np][0]), "=r"(bfr[2*np][1]),
                      "=r"(bfr[2*np+1][0]), "=r"(bfr[2*np+1][1])
                    : "r"(addr));
            }
            #pragma unroll
            for (int mt = 0; mt < 4; mt++)
                #pragma unroll
                for (int nt = 0; nt < 4; nt++) {
                    asm volatile(
                        "mma.sync.aligned.m16n8k16.row.col.f32.bf16.bf16.f32 "
                        "{%0,%1,%2,%3},{%4,%5,%6,%7},{%8,%9},{%0,%1,%2,%3};\n"
                        : "+f"(acc[mt][nt][0]), "+f"(acc[mt][nt][1]),
                          "+f"(acc[mt][nt][2]), "+f"(acc[mt][nt][3])
                        : "r"(af[mt][0]), "r"(af[mt][1]), "r"(af[mt][2]), "r"(af[mt][3]),
                          "r"(bfr[nt][0]), "r"(bfr[nt][1]));
                }
        }
    }

    #pragma unroll
    for (int mt = 0; mt < 4; mt++)
        #pragma unroll
        for (int nt = 0; nt < 4; nt++) {
            int r0 = wm + mt * 16 + gq;
            int c0 = n0 + wn + nt * 8 + tg * 2;
            #pragma unroll
            for (int e = 0; e < 4; e++) {
                int r = r0 + (e >> 1) * 8;
                int c = c0 + (e & 1);
                g_lkv_part[z][r * HIDD + c] = acc[mt][nt][e];
            }
        }
}

// ---------- fused QUAD+LOUT (bf16): A [m][k] ldmatrix, B [k][n] ldmatrix.trans ----------

#define QA 5120                        // A bf16/stage (128*40)
#define QB 4352                        // B bf16/stage (32*136)
#define SMEM_QL ((QA + QB) * 3 * 2)    // 56832 bytes

__global__ void __launch_bounds__(256, 2)
gemm_ql_kernel() {
    int z = blockIdx.z;          // group 0..63
    int b = z >> 4;              // batch
    const bf16* A1 = g_attnb + (size_t)z * GRP * GRP;   // [m][k], lda GRP
    const bf16* B1 = g_vb    + (size_t)z * GRP * HIDD;  // [k][n]
    const bf16* A2 = g_lqb   + (size_t)z * GRP * QKD;   // [m][k], lda QKD
    const bf16* B2 = g_lkvb  + (size_t)b * QKD * HIDD;  // [k][n]

    extern __shared__ bf16 hsm[];
    bf16* Abuf = hsm;
    bf16* Bbuf = hsm + 3 * QA;

    int tid = threadIdx.x;
    int m0 = blockIdx.y * 128, n0 = blockIdx.x * 128;
    int wid = tid >> 5, lane = tid & 31;
    int wm = (wid >> 2) * 64, wn = (wid & 3) * 32;
    int gq = lane >> 2, tg = lane & 3;
    int lrow = lane & 7, lmat = lane >> 3;

    auto load_tiles = [&](int stage, int slab) {
        bf16* As = Abuf + stage * QA;
        bf16* Bs = Bbuf + stage * QB;
        const bf16* A; const bf16* B; int lda, k0;
        if (slab < 8) { A = A1; lda = GRP; k0 = slab * 32; B = B1 + (size_t)k0 * HIDD; }
        else          { A = A2; lda = QKD; k0 = (slab - 8) * 32; B = B2 + (size_t)k0 * HIDD; }
        #pragma unroll
        for (int r = 0; r < 2; r++) {             // A: 128 rows x 4 chunks (32 k)
            int chunk = tid + r * 256;
            int row = chunk >> 2, cc = (chunk & 3) * 8;
            cpa16(&As[row * 40 + cc], A + (size_t)(m0 + row) * lda + k0 + cc);
        }
        #pragma unroll
        for (int r = 0; r < 2; r++) {             // B: 32 k-rows x 16 chunks
            int chunk = tid + r * 256;
            int row = chunk >> 4, cc = (chunk & 15) * 8;
            cpa16(&Bs[row * LSTR + cc], B + (size_t)row * HIDD + n0 + cc);
        }
    };

    float acc[4][4][4];
    #pragma unroll
    for (int i = 0; i < 4; i++)
        #pragma unroll
        for (int j = 0; j < 4; j++)
            #pragma unroll
            for (int k = 0; k < 4; k++) acc[i][j][k] = 0.0f;

    const int nSlab = 12;        // 8 (attn@v) + 4 (lq@lkv)
    load_tiles(0, 0);
    asm volatile("cp.async.commit_group;\n" ::);
    load_tiles(1, 1);
    asm volatile("cp.async.commit_group;\n" ::);

    for (int i = 0; i < nSlab; i++) {
        asm volatile("cp.async.wait_group 1;\n" ::);
        __syncthreads();
        if (i + 2 < nSlab) {
            load_tiles((i + 2) % 3, i + 2);
            asm volatile("cp.async.commit_group;\n" ::);
        } else {
            asm volatile("cp.async.commit_group;\n" ::);
        }

        const bf16* As = Abuf + (i % 3) * QA;
        const bf16* Bs = Bbuf + (i % 3) * QB;

        #pragma unroll
        for (int ks = 0; ks < 32; ks += 16) {
            uint32_t af[4][4], bfr[4][2];
            #pragma unroll
            for (int mt = 0; mt < 4; mt++) {      // A: non-trans ([m][k] source, R8 proven)
                const bf16* p = &As[(size_t)(wm + mt * 16 + lrow + (lmat & 1) * 8) * 40
                                    + ks + (lmat >> 1) * 8];
                uint32_t addr = (uint32_t)__cvta_generic_to_shared(p);
                asm volatile(
                    "ldmatrix.sync.aligned.m8n8.x4.shared.b16 {%0,%1,%2,%3}, [%4];\n"
                    : "=r"(af[mt][0]), "=r"(af[mt][1]), "=r"(af[mt][2]), "=r"(af[mt][3])
                    : "r"(addr));
            }
            #pragma unroll
            for (int np = 0; np < 2; np++) {      // B: trans ([k][n] source)
                const bf16* p = &Bs[(size_t)(ks + (lmat & 1) * 8 + lrow) * LSTR
                                    + wn + np * 16 + (lmat >> 1) * 8];
                uint32_t addr = (uint32_t)__cvta_generic_to_shared(p);
                asm volatile(
                    "ldmatrix.sync.aligned.m8n8.x4.trans.shared.b16 {%0,%1,%2,%3}, [%4];\n"
                    : "=r"(bfr[2*np][0]), "=r"(bfr[2*np][1]),
                      "=r"(bfr[2*np+1][0]), "=r"(bfr[2*np+1][1])
                    : "r"(addr));
            }
            #pragma unroll
            for (int mt = 0; mt < 4; mt++)
                #pragma unroll
                for (int nt = 0; nt < 4; nt++) {
                    asm volatile(
                        "mma.sync.aligned.m16n8k16.row.col.f32.bf16.bf16.f32 "
                        "{%0,%1,%2,%3},{%4,%5,%6,%7},{%8,%9},{%0,%1,%2,%3};\n"
                        : "+f"(acc[mt][nt][0]), "+f"(acc[mt][nt][1]),
                          "+f"(acc[mt][nt][2]), "+f"(acc[mt][nt][3])
                        : "r"(af[mt][0]), "r"(af[mt][1]), "r"(af[mt][2]), "r"(af[mt][3]),
                          "r"(bfr[nt][0]), "r"(bfr[nt][1]));
                }
        }
    }

    #pragma unroll
    for (int mt = 0; mt < 4; mt++)
        #pragma unroll
        for (int nt = 0; nt < 4; nt++) {
            int r0 = m0 + wm + mt * 16 + gq;     // row within group (0..255)
            int c0 = n0 + wn + nt * 8 + tg * 2;
            #pragma unroll
            for (int e = 0; e < 4; e++) {
                int r = r0 + (e >> 1) * 8;
                int c = c0 + (e & 1);
                size_t o = ((size_t)z * GRP + r) * HIDD + c;
                g_gatedb[o] = __float2bfloat16(g_gate[o] * acc[mt][nt][e]);
            }
        }
}

// ---------- BF16 GEMM (G1, FIN): 128x128, 3-stage + ldmatrix (R8 proven) ----------

#define HSTRIDE 5120   // bf16 elems per stage per operand (128*40)
#define SMEM_BF (6 * HSTRIDE * 2)   // 61440

template<int MODE>
__global__ void __launch_bounds__(256, 2)
gemm_bf16_kernel(const float* __restrict__ p0, const float* __restrict__ p2,
                 float* __restrict__ pf) {
    const bf16* A; const bf16* B; int K;
    if constexpr (MODE == M_G1) { A = g_normedb; B = g_Whb; K = DIMD; }
    else                        { A = g_gatedb;  B = g_Wob; K = HIDD; }

    extern __shared__ bf16 hsm[];
    bf16* Abuf = hsm;
    bf16* Bbuf = hsm + 3 * HSTRIDE;

    int tid = threadIdx.x;
    int m0 = blockIdx.y * 128, n0 = blockIdx.x * 128;
    int wid = tid >> 5, lane = tid & 31;
    int wm = (wid >> 2) * 64, wn = (wid & 3) * 32;
    int gq = lane >> 2, tg = lane & 3;
    int lrow = lane & 7, lmat = lane >> 3;

    auto load_tiles = [&](int stage, int k0) {
        bf16* As = Abuf + stage * HSTRIDE;
        bf16* Bs = Bbuf + stage * HSTRIDE;
        #pragma unroll
        for (int r = 0; r < 2; r++) {
            int chunk = tid + r * 256;
            int row = chunk >> 2, cc = (chunk & 3) * 8;
            cpa16(&As[row * 40 + cc], A + (size_t)(m0 + row) * K + k0 + cc);
        }
        #pragma unroll
        for (int r = 0; r < 2; r++) {
            int chunk = tid + r * 256;
            int row = chunk >> 2, cc = (chunk & 3) * 8;
            cpa16(&Bs[row * 40 + cc], B + (size_t)(n0 + row) * K + k0 + cc);
        }
    };

    float acc[4][4][4];
    #pragma unroll
    for (int i = 0; i < 4; i++)
        #pragma unroll
        for (int j = 0; j < 4; j++)
            #pragma unroll
            for (int k = 0; k < 4; k++) acc[i][j][k] = 0.0f;

    int nK = K >> 5;
    load_tiles(0, 0);
    asm volatile("cp.async.commit_group;\n" ::);
    load_tiles(1, 32);
    asm volatile("cp.async.commit_group;\n" ::);

    for (int i = 0; i < nK; i++) {
        asm volatile("cp.async.wait_group 1;\n" ::);
        __syncthreads();
        if (i + 2 < nK) {
            load_tiles((i + 2) % 3, (i + 2) * 32);
            asm volatile("cp.async.commit_group;\n" ::);
        } else {
            asm volatile("cp.async.commit_group;\n" ::);
        }

        const bf16* As = Abuf + (i % 3) * HSTRIDE;
        const bf16* Bs = Bbuf + (i % 3) * HSTRIDE;

        #pragma unroll
        for (int ks = 0; ks < 32; ks += 16) {
            uint32_t af[4][4], bfr[4][2];
            #pragma unroll
            for (int mt = 0; mt < 4; mt++) {
                const bf16* p = &As[(size_t)(wm + mt * 16 + lrow + (lmat & 1) * 8) * 40
                                    + ks + (lmat >> 1) * 8];
                uint32_t addr = (uint32_t)__cvta_generic_to_shared(p);
                asm volatile(
                    "ldmatrix.sync.aligned.m8n8.x4.shared.b16 {%0,%1,%2,%3}, [%4];\n"
                    : "=r"(af[mt][0]), "=r"(af[mt][1]), "=r"(af[mt][2]), "=r"(af[mt][3])
                    : "r"(addr));
            }
            #pragma unroll
            for (int np = 0; np < 2; np++) {
                const bf16* p = &Bs[(size_t)(wn + np * 16 + lrow + (lmat >> 1) * 8) * 40
                                    + ks + (lmat & 1) * 8];
                uint32_t addr = (uint32_t)__cvta_generic_to_shared(p);
                asm volatile(
                    "ldmatrix.sync.aligned.m8n8.x4.shared.b16 {%0,%1,%2,%3}, [%4];\n"
                    : "=r"(bfr[2*np][0]), "=r"(bfr[2*np][1]),
                      "=r"(bfr[2*np+1][0]), "=r"(bfr[2*np+1][1])
                    : "r"(addr));
            }
            #pragma unroll
            for (int mt = 0; mt < 4; mt++)
                #pragma unroll
                for (int nt = 0; nt < 4; nt++) {
                    asm volatile(
                        "mma.sync.aligned.m16n8k16.row.col.f32.bf16.bf16.f32 "
                        "{%0,%1,%2,%3},{%4,%5,%6,%7},{%8,%9},{%0,%1,%2,%3};\n"
                        : "+f"(acc[mt][nt][0]), "+f"(acc[mt][nt][1]),
                          "+f"(acc[mt][nt][2]), "+f"(acc[mt][nt][3])
                        : "r"(af[mt][0]), "r"(af[mt][1]), "r"(af[mt][2]), "r"(af[mt][3]),
                          "r"(bfr[nt][0]), "r"(bfr[nt][1]));
                }
        }
    }

    #pragma unroll
    for (int mt = 0; mt < 4; mt++)
        #pragma unroll
        for (int nt = 0; nt < 4; nt++) {
            int r0 = m0 + wm + mt * 16 + gq;
            int c0 = n0 + wn + nt * 8 + tg * 2;
            #pragma unroll
            for (int e = 0; e < 4; e++) {
                int r = r0 + (e >> 1) * 8;
                int c = c0 + (e & 1);
                float a = acc[mt][nt][e];
                if constexpr (MODE == M_G1) {
                    float h = siluf(a + p0[c]);
                    if (c < HIDD) g_vb[(size_t)r * HIDD + c] = __float2bfloat16(h);
                    else          g_gate[(size_t)r * HIDD + (c - HIDD)] = h;
                } else {
                    size_t o = (size_t)r * DIMD + c;
                    pf[o] = a + p0[c] + p2[o];
                }
            }
        }
}

// ---------------- launch ----------------

extern "C" void kernel_launch(void* const* d_in, const int* in_sizes, int n_in,
                              void* d_out, int out_size) {
    const float* x     = (const float*)d_in[0];
    const float* ln_g  = (const float*)d_in[1];
    const float* ln_b  = (const float*)d_in[2];
    const float* W_h   = (const float*)d_in[3];
    const float* b_h   = (const float*)d_in[4];
    const float* W_qk  = (const float*)d_in[5];
    const float* b_qk  = (const float*)d_in[6];
    const float* gam   = (const float*)d_in[7];
    const float* bet   = (const float*)d_in[8];
    const float* rel   = (const float*)d_in[9];
    const float* W_out = (const float*)d_in[10];
    const float* b_out = (const float*)d_in[11];
    float* out = (float*)d_out;

    (void)in_sizes; (void)n_in; (void)out_size;

    static cudaStream_t s_side = nullptr;
    static cudaEvent_t ev_fork = nullptr, ev_prep = nullptr, ev_ln = nullptr,
                       ev_g2 = nullptr, ev_sim = nullptr;
    if (!s_side) {
        cudaStreamCreateWithFlags(&s_side, cudaStreamNonBlocking);
        cudaEventCreateWithFlags(&ev_fork, cudaEventDisableTiming);
        cudaEventCreateWithFlags(&ev_prep, cudaEventDisableTiming);
        cudaEventCreateWithFlags(&ev_ln,   cudaEventDisableTiming);
        cudaEventCreateWithFlags(&ev_g2,   cudaEventDisableTiming);
        cudaEventCreateWithFlags(&ev_sim,  cudaEventDisableTiming);
        cudaFuncSetAttribute(gemm_kernel<M_G2>,  cudaFuncAttributeMaxDynamicSharedMemorySize, SMEM_T3);
        cudaFuncSetAttribute(gemm_kernel<M_SIM>, cudaFuncAttributeMaxDynamicSharedMemorySize, SMEM_T3);
        cudaFuncSetAttribute(gemm_lkv_kernel,    cudaFuncAttributeMaxDynamicSharedMemorySize, SMEM_LKV);
        cudaFuncSetAttribute(gemm_ql_kernel,     cudaFuncAttributeMaxDynamicSharedMemorySize, SMEM_QL);
        cudaFuncSetAttribute(gemm_bf16_kernel<M_G1>, cudaFuncAttributeMaxDynamicSharedMemorySize, SMEM_BF);
        cudaFuncSetAttribute(gemm_bf16_kernel<M_FIN>,cudaFuncAttributeMaxDynamicSharedMemorySize, SMEM_BF);
    }

    // fork; prep on side while ln runs on main
    cudaEventRecord(ev_fork, 0);
    cudaStreamWaitEvent(s_side, ev_fork, 0);

    wtrans_kernel<<<dim3(128, 32), dim3(32, 8), 0, s_side>>>(W_h, 0, DIMD, 2*HIDD);
    wtrans_kernel<<<dim3(32, 64),  dim3(32, 8), 0, s_side>>>(W_out, 1, HIDD, DIMD);
    wqk_round_kernel<<<(DIMD*QKD)/256, 256, 0, s_side>>>(W_qk);
    bias_kernel<<<(GRP*GRP)/256, 256, 0, s_side>>>(rel);
    cudaEventRecord(ev_prep, s_side);

    ln_kernel<<<TOK, 256>>>(x, ln_g, ln_b);
    cudaEventRecord(ev_ln, 0);

    // side: G2 -> SIM (overlaps G1 on main)
    cudaStreamWaitEvent(s_side, ev_ln, 0);
    gemm_kernel<M_G2> <<<dim3(1, 128, 1),  256, SMEM_T3, s_side>>>(b_qk, gam, bet);
    cudaEventRecord(ev_g2, s_side);
    gemm_kernel<M_SIM><<<dim3(2, 2, NGRP), 256, SMEM_T3, s_side>>>(nullptr, nullptr, nullptr);
    cudaEventRecord(ev_sim, s_side);

    // main: G1 (128x128, 2 CTA/SM)
    cudaStreamWaitEvent(0, ev_prep, 0);
    gemm_bf16_kernel<M_G1><<<dim3(32, 128), 256, SMEM_BF>>>(b_h, nullptr, nullptr);

    // main: LKV (bf16; needs vb from G1, lkhb from G2)
    cudaStreamWaitEvent(0, ev_g2, 0);
    gemm_lkv_kernel<<<dim3(16, 1, 16), 256, SMEM_LKV>>>();
    lkv_reduce_kernel<<<(4*QKD*HIDD)/256, 256>>>();

    // main: fused QUAD+LOUT (bf16; needs attnb, lkvb, gate, lqb)
    cudaStreamWaitEvent(0, ev_sim, 0);
    gemm_ql_kernel<<<dim3(16, 2, NGRP), 256, SMEM_QL>>>();

    // main: FIN
    gemm_bf16_kernel<M_FIN><<<dim3(8, 128), 256, SMEM_BF>>>(b_out, x, out);
}

// round 15
// speedup vs baseline: 1.4245x; 1.0846x over previous
#include <cuda_runtime.h>
#include <cuda_bf16.h>
#include <math.h>
#include <stdint.h>

typedef __nv_bfloat16 bf16;

#define TOK   16384
#define DIMD  1024
#define HIDD  2048
#define QKD   128
#define GRP   256
#define NGRP  64
#define NPB   4096

// ---------------- device scratch ----------------
__device__ float g_normed[TOK * DIMD];              // tf32-rounded (G2 operand)
__device__ bf16  g_normedb[TOK * DIMD];             // bf16 copy (G1 operand)
__device__ bf16  g_Whb[2 * HIDD * DIMD];            // W_h transposed [n][k] bf16
__device__ bf16  g_Wob[DIMD * HIDD];                // W_out transposed [n][k] bf16
__device__ float g_Wqkr[DIMD * QKD];                // W_qk tf32-rounded
__device__ bf16  g_vb[TOK * HIDD];                  // bf16 (QL/LKV B operand)
__device__ float g_gate[TOK * HIDD];                // fp32 (output-product path!)
__device__ float g_qq[TOK * QKD];                   // tf32 (SIM operand - precision critical)
__device__ bf16  g_lqb[TOK * QKD];                  // bf16 (QL lin operand)
__device__ float g_qkh[TOK * QKD];                  // tf32 (SIM operand - precision critical)
__device__ bf16  g_lkhb[TOK * QKD];                 // bf16 (LKV operand)
__device__ float g_bias[GRP * GRP];
__device__ bf16  g_attnb[(size_t)NGRP * GRP * GRP]; // bf16 (QL quad operand)
__device__ float g_lkv_part[16][QKD * HIDD];        // fp32 partials
__device__ bf16  g_lkvb[4 * QKD * HIDD];            // bf16 (QL lin B operand)
__device__ bf16  g_gatedb[TOK * HIDD];              // bf16 (FIN operand)

__device__ __forceinline__ float rna_tf32(float x) {
    float y;
    asm("cvt.rna.tf32.f32 %0, %1;\n" : "=f"(y) : "f"(x));
    return y;
}

// ---------------- small kernels ----------------

__global__ void bias_kernel(const float* __restrict__ rel_emb) {
    int idx = blockIdx.x * blockDim.x + threadIdx.x;
    int i = idx >> 8, j = idx & 255;
    int n = i - j;
    int ret = (n < 0) ? 16 : 0;
    int na = abs(n);
    int bucket;
    if (na < 8) {
        bucket = ret + na;
    } else {
        float t = logf((float)na * 0.125f) / 2.7725887298583984f;
        t = t * 8.0f;
        float r = rintf(t);
        int ti = (fabsf(t - r) < 1e-3f) ? (int)r : (int)t;
        int vl = 8 + ti;
        if (vl > 15) vl = 15;
        bucket = ret + vl;
    }
    g_bias[idx] = rel_emb[bucket] * 11.313708498984761f;
}

// 32x32 tiled transpose+convert: src f32 [K][N] -> dst bf16 [N][K]
__global__ void wtrans_kernel(const float* __restrict__ src, int which, int K, int N) {
    bf16* dst = (which == 0) ? g_Whb : g_Wob;
    __shared__ float t[32][33];
    int n0 = blockIdx.x * 32, k0 = blockIdx.y * 32;
    int tx = threadIdx.x, ty = threadIdx.y;
    #pragma unroll
    for (int i = 0; i < 4; i++)
        t[ty + 8*i][tx] = src[(size_t)(k0 + ty + 8*i) * N + n0 + tx];
    __syncthreads();
    #pragma unroll
    for (int i = 0; i < 4; i++)
        dst[(size_t)(n0 + ty + 8*i) * K + k0 + tx] = __float2bfloat16(t[tx][ty + 8*i]);
}

__global__ void wqk_round_kernel(const float* __restrict__ src) {
    int i = blockIdx.x * blockDim.x + threadIdx.x;
    g_Wqkr[i] = rna_tf32(src[i]);
}

__global__ void ln_kernel(const float* __restrict__ x,
                          const float* __restrict__ gw,
                          const float* __restrict__ bw) {
    int row = blockIdx.x;
    int t = threadIdx.x;
    const float4* xr = (const float4*)(x + (size_t)row * DIMD);
    float4 v = xr[t];
    float s  = v.x + v.y + v.z + v.w;
    float s2 = v.x*v.x + v.y*v.y + v.z*v.z + v.w*v.w;
    #pragma unroll
    for (int o = 16; o; o >>= 1) {
        s  += __shfl_xor_sync(0xffffffffu, s,  o);
        s2 += __shfl_xor_sync(0xffffffffu, s2, o);
    }
    __shared__ float sm[8], sm2[8];
    int w = t >> 5;
    if ((t & 31) == 0) { sm[w] = s; sm2[w] = s2; }
    __syncthreads();
    float ts = 0.f, ts2 = 0.f;
    #pragma unroll
    for (int k = 0; k < 8; k++) { ts += sm[k]; ts2 += sm2[k]; }
    float mu   = ts  * (1.0f / DIMD);
    float var  = ts2 * (1.0f / DIMD) - mu * mu;
    float rstd = rsqrtf(var + 1e-5f);
    float4 gv = ((const float4*)gw)[t];
    float4 bv = ((const float4*)bw)[t];
    float o0 = (v.x - mu) * rstd * gv.x + bv.x;
    float o1 = (v.y - mu) * rstd * gv.y + bv.y;
    float o2 = (v.z - mu) * rstd * gv.z + bv.z;
    float o3 = (v.w - mu) * rstd * gv.w + bv.w;
    float4 o; o.x = rna_tf32(o0); o.y = rna_tf32(o1); o.z = rna_tf32(o2); o.w = rna_tf32(o3);
    ((float4*)(g_normed + (size_t)row * DIMD))[t] = o;
    bf16* ob = g_normedb + (size_t)row * DIMD + t * 4;
    ob[0] = __float2bfloat16(o0); ob[1] = __float2bfloat16(o1);
    ob[2] = __float2bfloat16(o2); ob[3] = __float2bfloat16(o3);
}

__global__ void lkv_reduce_kernel() {
    int idx = blockIdx.x * blockDim.x + threadIdx.x;
    int b = idx >> 18;
    int r = idx & ((1 << 18) - 1);
    float s = g_lkv_part[b*4+0][r] + g_lkv_part[b*4+1][r]
            + g_lkv_part[b*4+2][r] + g_lkv_part[b*4+3][r];
    g_lkvb[idx] = __float2bfloat16(s * (1.0f / NPB));
}

// ---------------- shared helpers ----------------

enum { M_G1 = 0, M_G2, M_SIM, M_FIN };

__device__ __forceinline__ float siluf(float x) { return x / (1.0f + expf(-x)); }

__device__ __forceinline__ void cpa16(void* dst, const void* src) {
    uint32_t d = (uint32_t)__cvta_generic_to_shared(dst);
    asm volatile("cp.async.cg.shared.global [%0], [%1], 16;\n" :: "r"(d), "l"(src));
}

// ---------------- TF32 GEMM (G2 / SIM): 128x128, 3-stage ----------------

template<int MODE>
__device__ __forceinline__ void epi(int r, int c, float a, int z,
                                    const float* p0, const float* p1,
                                    const float* p2) {
    if constexpr (MODE == M_G2) {
        float q = siluf(a + p0[c]);
        size_t o = (size_t)r * QKD + c;
        g_qq[o]   = rna_tf32(q * p1[0*QKD + c] + p2[0*QKD + c]);
        g_lqb[o]  = __float2bfloat16(q * p1[1*QKD + c] + p2[1*QKD + c]);
        g_qkh[o]  = rna_tf32(q * p1[2*QKD + c] + p2[2*QKD + c]);
        g_lkhb[o] = __float2bfloat16(q * p1[3*QKD + c] + p2[3*QKD + c]);
    } else if constexpr (MODE == M_SIM) {
        float s = a * (1.0f / GRP) + g_bias[r * GRP + c];
        s = fmaxf(s, 0.0f);
        g_attnb[(size_t)z * GRP * GRP + r * GRP + c] = __float2bfloat16(s * s);
    }
}

#define TSTRIDE 4608
#define SMEM_T3 (6 * TSTRIDE * 4)   // 110592: 3 stages x 2 operands

template<int MODE>
__global__ void __launch_bounds__(256, 2)
gemm_kernel(const float* __restrict__ p0, const float* __restrict__ p1,
            const float* __restrict__ p2) {
    const float* A; const float* B; int K, lda, ldb;
    int z = blockIdx.z;
    if constexpr (MODE == M_G2) { A = g_normed; B = g_Wqkr; K = DIMD; lda = DIMD; ldb = QKD; }
    else                        { A = g_qq  + (size_t)z*GRP*QKD; B = g_qkh + (size_t)z*GRP*QKD; K = QKD; lda = QKD; ldb = QKD; }

    constexpr bool TB = (MODE == M_SIM);   // B stored N x K  -> smem [n][k]

    extern __shared__ float smem[];
    float* Abuf = smem;
    float* Bbuf = smem + 3 * TSTRIDE;

    int tid = threadIdx.x;
    int m0 = blockIdx.y * 128, n0 = blockIdx.x * 128;
    int wid = tid >> 5, lane = tid & 31;
    int wm = (wid >> 2) * 64, wn = (wid & 3) * 32;
    int gq = lane >> 2, tg = lane & 3;

    auto load_tiles = [&](int stage, int k0) {
        float* As = Abuf + stage * TSTRIDE;
        float* Bs = Bbuf + stage * TSTRIDE;
        #pragma unroll
        for (int r = 0; r < 4; r++) {
            int chunk = tid + r * 256;
            int row = chunk >> 3, cc = (chunk & 7) * 4;
            cpa16(&As[row * 36 + cc], A + (size_t)(m0 + row) * lda + k0 + cc);
        }
        if constexpr (TB) {
            #pragma unroll
            for (int r = 0; r < 4; r++) {
                int chunk = tid + r * 256;
                int row = chunk >> 3, cc = (chunk & 7) * 4;
                cpa16(&Bs[row * 36 + cc], B + (size_t)(n0 + row) * ldb + k0 + cc);
            }
        } else {
            #pragma unroll
            for (int r = 0; r < 4; r++) {
                int chunk = tid + r * 256;
                int row = chunk >> 5, cc = (chunk & 31) * 4;
                cpa16(&Bs[row * 132 + cc], B + (size_t)(k0 + row) * ldb + n0 + cc);
            }
        }
    };

    float acc[4][4][4];
    #pragma unroll
    for (int i = 0; i < 4; i++)
        #pragma unroll
        for (int j = 0; j < 4; j++)
            #pragma unroll
            for (int k = 0; k < 4; k++) acc[i][j][k] = 0.0f;

    int nK = K >> 5;
    load_tiles(0, 0);
    asm volatile("cp.async.commit_group;\n" ::);
    load_tiles(1, 32);
    asm volatile("cp.async.commit_group;\n" ::);

    for (int i = 0; i < nK; i++) {
        asm volatile("cp.async.wait_group 1;\n" ::);
        __syncthreads();
        if (i + 2 < nK) {
            load_tiles((i + 2) % 3, (i + 2) * 32);
            asm volatile("cp.async.commit_group;\n" ::);
        } else {
            asm volatile("cp.async.commit_group;\n" ::);
        }

        const float* As = Abuf + (i % 3) * TSTRIDE;
        const float* Bs = Bbuf + (i % 3) * TSTRIDE;

        #pragma unroll
        for (int ks = 0; ks < 32; ks += 8) {
            uint32_t af[4][4], bfr[4][2];
            #pragma unroll
            for (int mt = 0; mt < 4; mt++) {
                int r0 = wm + mt * 16 + gq;
                af[mt][0] = *(const uint32_t*)&As[(r0    ) * 36 + ks + tg];
                af[mt][1] = *(const uint32_t*)&As[(r0 + 8) * 36 + ks + tg];
                af[mt][2] = *(const uint32_t*)&As[(r0    ) * 36 + ks + tg + 4];
                af[mt][3] = *(const uint32_t*)&As[(r0 + 8) * 36 + ks + tg + 4];
            }
            #pragma unroll
            for (int nt = 0; nt < 4; nt++) {
                int c0 = wn + nt * 8 + gq;
                if constexpr (TB) {
                    bfr[nt][0] = *(const uint32_t*)&Bs[c0 * 36 + ks + tg];
                    bfr[nt][1] = *(const uint32_t*)&Bs[c0 * 36 + ks + tg + 4];
                } else {
                    bfr[nt][0] = *(const uint32_t*)&Bs[(ks + tg    ) * 132 + c0];
                    bfr[nt][1] = *(const uint32_t*)&Bs[(ks + tg + 4) * 132 + c0];
                }
            }
            #pragma unroll
            for (int mt = 0; mt < 4; mt++)
                #pragma unroll
                for (int nt = 0; nt < 4; nt++) {
                    asm volatile(
                        "mma.sync.aligned.m16n8k8.row.col.f32.tf32.tf32.f32 "
                        "{%0,%1,%2,%3},{%4,%5,%6,%7},{%8,%9},{%0,%1,%2,%3};\n"
                        : "+f"(acc[mt][nt][0]), "+f"(acc[mt][nt][1]),
                          "+f"(acc[mt][nt][2]), "+f"(acc[mt][nt][3])
                        : "r"(af[mt][0]), "r"(af[mt][1]), "r"(af[mt][2]), "r"(af[mt][3]),
                          "r"(bfr[nt][0]), "r"(bfr[nt][1]));
                }
        }
    }

    #pragma unroll
    for (int mt = 0; mt < 4; mt++)
        #pragma unroll
        for (int nt = 0; nt < 4; nt++) {
            int r0 = m0 + wm + mt * 16 + gq;
            int c0 = n0 + wn + nt * 8 + tg * 2;
            epi<MODE>(r0,     c0,     acc[mt][nt][0], z, p0, p1, p2);
            epi<MODE>(r0,     c0 + 1, acc[mt][nt][1], z, p0, p1, p2);
            epi<MODE>(r0 + 8, c0,     acc[mt][nt][2], z, p0, p1, p2);
            epi<MODE>(r0 + 8, c0 + 1, acc[mt][nt][3], z, p0, p1, p2);
        }
}

// ---------- LKV (bf16): lin_kv partials, A=[k][m] + B=[k][n] via ldmatrix.trans ----------

#define LSTR 136                      // bf16 row stride for [k][*] tiles
#define LSTG (32 * LSTR)              // 4352 bf16 per operand-stage
#define SMEM_LKV (LSTG * 2 * 3 * 2)   // 52224 bytes

__global__ void __launch_bounds__(256, 2)
gemm_lkv_kernel() {
    int z = blockIdx.z;
    int b = z >> 2, kspl = z & 3;
    const bf16* A = g_lkhb + (size_t)(b*NPB + kspl*1024)*QKD;   // [k][m] (token x qk)
    const bf16* B = g_vb   + (size_t)(b*NPB + kspl*1024)*HIDD;  // [k][n] (token x hid)
    int n0 = blockIdx.x * 128;

    extern __shared__ bf16 hsm[];
    bf16* Abuf = hsm;
    bf16* Bbuf = hsm + 3 * LSTG;

    int tid = threadIdx.x;
    int wid = tid >> 5, lane = tid & 31;
    int wm = (wid >> 2) * 64, wn = (wid & 3) * 32;
    int gq = lane >> 2, tg = lane & 3;
    int lrow = lane & 7, lmat = lane >> 3;

    auto load_tiles = [&](int stage, int k0) {
        bf16* As = Abuf + stage * LSTG;
        bf16* Bs = Bbuf + stage * LSTG;
        #pragma unroll
        for (int r = 0; r < 2; r++) {             // A: 32 k-rows x 16 chunks
            int chunk = tid + r * 256;
            int row = chunk >> 4, cc = (chunk & 15) * 8;
            cpa16(&As[row * LSTR + cc], A + (size_t)(k0 + row) * QKD + cc);
        }
        #pragma unroll
        for (int r = 0; r < 2; r++) {             // B: 32 k-rows x 16 chunks
            int chunk = tid + r * 256;
            int row = chunk >> 4, cc = (chunk & 15) * 8;
            cpa16(&Bs[row * LSTR + cc], B + (size_t)(k0 + row) * HIDD + n0 + cc);
        }
    };

    float acc[4][4][4];
    #pragma unroll
    for (int i = 0; i < 4; i++)
        #pragma unroll
        for (int j = 0; j < 4; j++)
            #pragma unroll
            for (int k = 0; k < 4; k++) acc[i][j][k] = 0.0f;

    const int nK = 32;                 // 1024 / 32
    load_tiles(0, 0);
    asm volatile("cp.async.commit_group;\n" ::);
    load_tiles(1, 32);
    asm volatile("cp.async.commit_group;\n" ::);

    for (int i = 0; i < nK; i++) {
        asm volatile("cp.async.wait_group 1;\n" ::);
        __syncthreads();
        if (i + 2 < nK) {
            load_tiles((i + 2) % 3, (i + 2) * 32);
            asm volatile("cp.async.commit_group;\n" ::);
        } else {
            asm volatile("cp.async.commit_group;\n" ::);
        }

        const bf16* As = Abuf + (i % 3) * LSTG;
        const bf16* Bs = Bbuf + (i % 3) * LSTG;

        #pragma unroll
        for (int ks = 0; ks < 32; ks += 16) {
            uint32_t af[4][4], bfr[4][2];
            #pragma unroll
            for (int mt = 0; mt < 4; mt++) {      // A: trans ([k][m] source)
                const bf16* p = &As[(size_t)(ks + (lmat >> 1) * 8 + lrow) * LSTR
                                    + wm + mt * 16 + (lmat & 1) * 8];
                uint32_t addr = (uint32_t)__cvta_generic_to_shared(p);
                asm volatile(
                    "ldmatrix.sync.aligned.m8n8.x4.trans.shared.b16 {%0,%1,%2,%3}, [%4];\n"
                    : "=r"(af[mt][0]), "=r"(af[mt][1]), "=r"(af[mt][2]), "=r"(af[mt][3])
                    : "r"(addr));
            }
            #pragma unroll
            for (int np = 0; np < 2; np++) {      // B: trans ([k][n] source)
                const bf16* p = &Bs[(size_t)(ks + (lmat & 1) * 8 + lrow) * LSTR
                                    + wn + np * 16 + (lmat >> 1) * 8];
                uint32_t addr = (uint32_t)__cvta_generic_to_shared(p);
                asm volatile(
                    "ldmatrix.sync.aligned.m8n8.x4.trans.shared.b16 {%0,%1,%2,%3}, [%4];\n"
                    : "=r"(bfr[2*np][0]), "=r"(bfr[2*np][1]),
                      "=r"(bfr[2*np+1][0]), "=r"(bfr[2*np+1][1])
                    : "r"(addr));
            }
            #pragma unroll
            for (int mt = 0; mt < 4; mt++)
                #pragma unroll
                for (int nt = 0; nt < 4; nt++) {
                    asm volatile(
                        "mma.sync.aligned.m16n8k16.row.col.f32.bf16.bf16.f32 "
                        "{%0,%1,%2,%3},{%4,%5,%6,%7},{%8,%9},{%0,%1,%2,%3};\n"
                        : "+f"(acc[mt][nt][0]), "+f"(acc[mt][nt][1]),
                          "+f"(acc[mt][nt][2]), "+f"(acc[mt][nt][3])
                        : "r"(af[mt][0]), "r"(af[mt][1]), "r"(af[mt][2]), "r"(af[mt][3]),
                          "r"(bfr[nt][0]), "r"(bfr[nt][1]));
                }
        }
    }

    #pragma unroll
    for (int mt = 0; mt < 4; mt++)
        #pragma unroll
        for (int nt = 0; nt < 4; nt++) {
            int r0 = wm + mt * 16 + gq;
            int c0 = n0 + wn + nt * 8 + tg * 2;
            #pragma unroll
            for (int e = 0; e < 4; e++) {
                int r = r0 + (e >> 1) * 8;
                int c = c0 + (e & 1);
                g_lkv_part[z][r * HIDD + c] = acc[mt][nt][e];
            }
        }
}

// ---------- fused QUAD+LOUT (bf16): A [m][k] ldmatrix, B [k][n] ldmatrix.trans ----------

#define QA 5120                        // A bf16/stage (128*40)
#define QB 4352                        // B bf16/stage (32*136)
#define SMEM_QL ((QA + QB) * 3 * 2)    // 56832 bytes

__global__ void __launch_bounds__(256, 2)
gemm_ql_kernel() {
    int z = blockIdx.z;          // group 0..63
    int b = z >> 4;              // batch
    const bf16* A1 = g_attnb + (size_t)z * GRP * GRP;   // [m][k], lda GRP
    const bf16* B1 = g_vb    + (size_t)z * GRP * HIDD;  // [k][n]
    const bf16* A2 = g_lqb   + (size_t)z * GRP * QKD;   // [m][k], lda QKD
    const bf16* B2 = g_lkvb  + (size_t)b * QKD * HIDD;  // [k][n]

    extern __shared__ bf16 hsm[];
    bf16* Abuf = hsm;
    bf16* Bbuf = hsm + 3 * QA;

    int tid = threadIdx.x;
    int m0 = blockIdx.y * 128, n0 = blockIdx.x * 128;
    int wid = tid >> 5, lane = tid & 31;
    int wm = (wid >> 2) * 64, wn = (wid & 3) * 32;
    int gq = lane >> 2, tg = lane & 3;
    int lrow = lane & 7, lmat = lane >> 3;

    auto load_tiles = [&](int stage, int slab) {
        bf16* As = Abuf + stage * QA;
        bf16* Bs = Bbuf + stage * QB;
        const bf16* A; const bf16* B; int lda, k0;
        if (slab < 8) { A = A1; lda = GRP; k0 = slab * 32; B = B1 + (size_t)k0 * HIDD; }
        else          { A = A2; lda = QKD; k0 = (slab - 8) * 32; B = B2 + (size_t)k0 * HIDD; }
        #pragma unroll
        for (int r = 0; r < 2; r++) {             // A: 128 rows x 4 chunks (32 k)
            int chunk = tid + r * 256;
            int row = chunk >> 2, cc = (chunk & 3) * 8;
            cpa16(&As[row * 40 + cc], A + (size_t)(m0 + row) * lda + k0 + cc);
        }
        #pragma unroll
        for (int r = 0; r < 2; r++) {             // B: 32 k-rows x 16 chunks
            int chunk = tid + r * 256;
            int row = chunk >> 4, cc = (chunk & 15) * 8;
            cpa16(&Bs[row * LSTR + cc], B + (size_t)row * HIDD + n0 + cc);
        }
    };

    float acc[4][4][4];
    #pragma unroll
    for (int i = 0; i < 4; i++)
        #pragma unroll
        for (int j = 0; j < 4; j++)
            #pragma unroll
            for (int k = 0; k < 4; k++) acc[i][j][k] = 0.0f;

    const int nSlab = 12;        // 8 (attn@v) + 4 (lq@lkv)
    load_tiles(0, 0);
    asm volatile("cp.async.commit_group;\n" ::);
    load_tiles(1, 1);
    asm volatile("cp.async.commit_group;\n" ::);

    for (int i = 0; i < nSlab; i++) {
        asm volatile("cp.async.wait_group 1;\n" ::);
        __syncthreads();
        if (i + 2 < nSlab) {
            load_tiles((i + 2) % 3, i + 2);
            asm volatile("cp.async.commit_group;\n" ::);
        } else {
            asm volatile("cp.async.commit_group;\n" ::);
        }

        const bf16* As = Abuf + (i % 3) * QA;
        const bf16* Bs = Bbuf + (i % 3) * QB;

        #pragma unroll
        for (int ks = 0; ks < 32; ks += 16) {
            uint32_t af[4][4], bfr[4][2];
            #pragma unroll
            for (int mt = 0; mt < 4; mt++) {      // A: non-trans ([m][k] source)
                const bf16* p = &As[(size_t)(wm + mt * 16 + lrow + (lmat & 1) * 8) * 40
                                    + ks + (lmat >> 1) * 8];
                uint32_t addr = (uint32_t)__cvta_generic_to_shared(p);
                asm volatile(
                    "ldmatrix.sync.aligned.m8n8.x4.shared.b16 {%0,%1,%2,%3}, [%4];\n"
                    : "=r"(af[mt][0]), "=r"(af[mt][1]), "=r"(af[mt][2]), "=r"(af[mt][3])
                    : "r"(addr));
            }
            #pragma unroll
            for (int np = 0; np < 2; np++) {      // B: trans ([k][n] source)
                const bf16* p = &Bs[(size_t)(ks + (lmat & 1) * 8 + lrow) * LSTR
                                    + wn + np * 16 + (lmat >> 1) * 8];
                uint32_t addr = (uint32_t)__cvta_generic_to_shared(p);
                asm volatile(
                    "ldmatrix.sync.aligned.m8n8.x4.trans.shared.b16 {%0,%1,%2,%3}, [%4];\n"
                    : "=r"(bfr[2*np][0]), "=r"(bfr[2*np][1]),
                      "=r"(bfr[2*np+1][0]), "=r"(bfr[2*np+1][1])
                    : "r"(addr));
            }
            #pragma unroll
            for (int mt = 0; mt < 4; mt++)
                #pragma unroll
                for (int nt = 0; nt < 4; nt++) {
                    asm volatile(
                        "mma.sync.aligned.m16n8k16.row.col.f32.bf16.bf16.f32 "
                        "{%0,%1,%2,%3},{%4,%5,%6,%7},{%8,%9},{%0,%1,%2,%3};\n"
                        : "+f"(acc[mt][nt][0]), "+f"(acc[mt][nt][1]),
                          "+f"(acc[mt][nt][2]), "+f"(acc[mt][nt][3])
                        : "r"(af[mt][0]), "r"(af[mt][1]), "r"(af[mt][2]), "r"(af[mt][3]),
                          "r"(bfr[nt][0]), "r"(bfr[nt][1]));
                }
        }
    }

    #pragma unroll
    for (int mt = 0; mt < 4; mt++)
        #pragma unroll
        for (int nt = 0; nt < 4; nt++) {
            int r0 = m0 + wm + mt * 16 + gq;     // row within group (0..255)
            int c0 = n0 + wn + nt * 8 + tg * 2;
            #pragma unroll
            for (int e = 0; e < 4; e++) {
                int r = r0 + (e >> 1) * 8;
                int c = c0 + (e & 1);
                size_t o = ((size_t)z * GRP + r) * HIDD + c;
                g_gatedb[o] = __float2bfloat16(g_gate[o] * acc[mt][nt][e]);
            }
        }
}

// ---------- BF16 GEMM (G1, FIN): 128x128, K-slab 64, 3-stage + ldmatrix ----------

#define HSTRIDE 9216   // bf16 elems per stage per operand (128 rows x 72: 64 K + 8 pad)
#define SMEM_BF (6 * HSTRIDE * 2)   // 110592

template<int MODE>
__global__ void __launch_bounds__(256, 2)
gemm_bf16_kernel(const float* __restrict__ p0, const float* __restrict__ p2,
                 float* __restrict__ pf) {
    const bf16* A; const bf16* B; int K;
    if constexpr (MODE == M_G1) { A = g_normedb; B = g_Whb; K = DIMD; }
    else                        { A = g_gatedb;  B = g_Wob; K = HIDD; }

    extern __shared__ bf16 hsm[];
    bf16* Abuf = hsm;
    bf16* Bbuf = hsm + 3 * HSTRIDE;

    int tid = threadIdx.x;
    int m0 = blockIdx.y * 128, n0 = blockIdx.x * 128;
    int wid = tid >> 5, lane = tid & 31;
    int wm = (wid >> 2) * 64, wn = (wid & 3) * 32;
    int gq = lane >> 2, tg = lane & 3;
    int lrow = lane & 7, lmat = lane >> 3;

    auto load_tiles = [&](int stage, int k0) {
        bf16* As = Abuf + stage * HSTRIDE;
        bf16* Bs = Bbuf + stage * HSTRIDE;
        #pragma unroll
        for (int r = 0; r < 4; r++) {            // A: 128 rows x 8 chunks (64 K)
            int chunk = tid + r * 256;
            int row = chunk >> 3, cc = (chunk & 7) * 8;
            cpa16(&As[row * 72 + cc], A + (size_t)(m0 + row) * K + k0 + cc);
        }
        #pragma unroll
        for (int r = 0; r < 4; r++) {            // B: 128 rows x 8 chunks
            int chunk = tid + r * 256;
            int row = chunk >> 3, cc = (chunk & 7) * 8;
            cpa16(&Bs[row * 72 + cc], B + (size_t)(n0 + row) * K + k0 + cc);
        }
    };

    float acc[4][4][4];
    #pragma unroll
    for (int i = 0; i < 4; i++)
        #pragma unroll
        for (int j = 0; j < 4; j++)
            #pragma unroll
            for (int k = 0; k < 4; k++) acc[i][j][k] = 0.0f;

    int nK = K >> 6;                   // 64-wide slabs
    load_tiles(0, 0);
    asm volatile("cp.async.commit_group;\n" ::);
    load_tiles(1, 64);
    asm volatile("cp.async.commit_group;\n" ::);

    for (int i = 0; i < nK; i++) {
        asm volatile("cp.async.wait_group 1;\n" ::);
        __syncthreads();
        if (i + 2 < nK) {
            load_tiles((i + 2) % 3, (i + 2) * 64);
            asm volatile("cp.async.commit_group;\n" ::);
        } else {
            asm volatile("cp.async.commit_group;\n" ::);
        }

        const bf16* As = Abuf + (i % 3) * HSTRIDE;
        const bf16* Bs = Bbuf + (i % 3) * HSTRIDE;

        #pragma unroll
        for (int ks = 0; ks < 64; ks += 16) {
            uint32_t af[4][4], bfr[4][2];
            #pragma unroll
            for (int mt = 0; mt < 4; mt++) {
                const bf16* p = &As[(size_t)(wm + mt * 16 + lrow + (lmat & 1) * 8) * 72
                                    + ks + (lmat >> 1) * 8];
                uint32_t addr = (uint32_t)__cvta_generic_to_shared(p);
                asm volatile(
                    "ldmatrix.sync.aligned.m8n8.x4.shared.b16 {%0,%1,%2,%3}, [%4];\n"
                    : "=r"(af[mt][0]), "=r"(af[mt][1]), "=r"(af[mt][2]), "=r"(af[mt][3])
                    : "r"(addr));
            }
            #pragma unroll
            for (int np = 0; np < 2; np++) {
                const bf16* p = &Bs[(size_t)(wn + np * 16 + lrow + (lmat >> 1) * 8) * 72
                                    + ks + (lmat & 1) * 8];
                uint32_t addr = (uint32_t)__cvta_generic_to_shared(p);
                asm volatile(
                    "ldmatrix.sync.aligned.m8n8.x4.shared.b16 {%0,%1,%2,%3}, [%4];\n"
                    : "=r"(bfr[2*np][0]), "=r"(bfr[2*np][1]),
                      "=r"(bfr[2*np+1][0]), "=r"(bfr[2*np+1][1])
                    : "r"(addr));
            }
            #pragma unroll
            for (int mt = 0; mt < 4; mt++)
                #pragma unroll
                for (int nt = 0; nt < 4; nt++) {
                    asm volatile(
                        "mma.sync.aligned.m16n8k16.row.col.f32.bf16.bf16.f32 "
                        "{%0,%1,%2,%3},{%4,%5,%6,%7},{%8,%9},{%0,%1,%2,%3};\n"
                        : "+f"(acc[mt][nt][0]), "+f"(acc[mt][nt][1]),
                          "+f"(acc[mt][nt][2]), "+f"(acc[mt][nt][3])
                        : "r"(af[mt][0]), "r"(af[mt][1]), "r"(af[mt][2]), "r"(af[mt][3]),
                          "r"(bfr[nt][0]), "r"(bfr[nt][1]));
                }
        }
    }

    #pragma unroll
    for (int mt = 0; mt < 4; mt++)
        #pragma unroll
        for (int nt = 0; nt < 4; nt++) {
            int r0 = m0 + wm + mt * 16 + gq;
            int c0 = n0 + wn + nt * 8 + tg * 2;
            #pragma unroll
            for (int e = 0; e < 4; e++) {
                int r = r0 + (e >> 1) * 8;
                int c = c0 + (e & 1);
                float a = acc[mt][nt][e];
                if constexpr (MODE == M_G1) {
                    float h = siluf(a + p0[c]);
                    if (c < HIDD) g_vb[(size_t)r * HIDD + c] = __float2bfloat16(h);
                    else          g_gate[(size_t)r * HIDD + (c - HIDD)] = h;
                } else {
                    size_t o = (size_t)r * DIMD + c;
                    pf[o] = a + p0[c] + p2[o];
                }
            }
        }
}

// ---------------- launch ----------------

extern "C" void kernel_launch(void* const* d_in, const int* in_sizes, int n_in,
                              void* d_out, int out_size) {
    const float* x     = (const float*)d_in[0];
    const float* ln_g  = (const float*)d_in[1];
    const float* ln_b  = (const float*)d_in[2];
    const float* W_h   = (const float*)d_in[3];
    const float* b_h   = (const float*)d_in[4];
    const float* W_qk  = (const float*)d_in[5];
    const float* b_qk  = (const float*)d_in[6];
    const float* gam   = (const float*)d_in[7];
    const float* bet   = (const float*)d_in[8];
    const float* rel   = (const float*)d_in[9];
    const float* W_out = (const float*)d_in[10];
    const float* b_out = (const float*)d_in[11];
    float* out = (float*)d_out;

    (void)in_sizes; (void)n_in; (void)out_size;

    static cudaStream_t s_side = nullptr;
    static cudaEvent_t ev_fork = nullptr, ev_prep = nullptr, ev_ln = nullptr,
                       ev_g2 = nullptr, ev_sim = nullptr;
    if (!s_side) {
        cudaStreamCreateWithFlags(&s_side, cudaStreamNonBlocking);
        cudaEventCreateWithFlags(&ev_fork, cudaEventDisableTiming);
        cudaEventCreateWithFlags(&ev_prep, cudaEventDisableTiming);
        cudaEventCreateWithFlags(&ev_ln,   cudaEventDisableTiming);
        cudaEventCreateWithFlags(&ev_g2,   cudaEventDisableTiming);
        cudaEventCreateWithFlags(&ev_sim,  cudaEventDisableTiming);
        cudaFuncSetAttribute(gemm_kernel<M_G2>,  cudaFuncAttributeMaxDynamicSharedMemorySize, SMEM_T3);
        cudaFuncSetAttribute(gemm_kernel<M_SIM>, cudaFuncAttributeMaxDynamicSharedMemorySize, SMEM_T3);
        cudaFuncSetAttribute(gemm_lkv_kernel,    cudaFuncAttributeMaxDynamicSharedMemorySize, SMEM_LKV);
        cudaFuncSetAttribute(gemm_ql_kernel,     cudaFuncAttributeMaxDynamicSharedMemorySize, SMEM_QL);
        cudaFuncSetAttribute(gemm_bf16_kernel<M_G1>, cudaFuncAttributeMaxDynamicSharedMemorySize, SMEM_BF);
        cudaFuncSetAttribute(gemm_bf16_kernel<M_FIN>,cudaFuncAttributeMaxDynamicSharedMemorySize, SMEM_BF);
    }

    // fork; prep on side while ln runs on main
    cudaEventRecord(ev_fork, 0);
    cudaStreamWaitEvent(s_side, ev_fork, 0);

    wtrans_kernel<<<dim3(128, 32), dim3(32, 8), 0, s_side>>>(W_h, 0, DIMD, 2*HIDD);
    wtrans_kernel<<<dim3(32, 64),  dim3(32, 8), 0, s_side>>>(W_out, 1, HIDD, DIMD);
    wqk_round_kernel<<<(DIMD*QKD)/256, 256, 0, s_side>>>(W_qk);
    bias_kernel<<<(GRP*GRP)/256, 256, 0, s_side>>>(rel);
    cudaEventRecord(ev_prep, s_side);

    ln_kernel<<<TOK, 256>>>(x, ln_g, ln_b);
    cudaEventRecord(ev_ln, 0);

    // side: G2 -> SIM (overlaps G1 on main)
    cudaStreamWaitEvent(s_side, ev_ln, 0);
    gemm_kernel<M_G2> <<<dim3(1, 128, 1),  256, SMEM_T3, s_side>>>(b_qk, gam, bet);
    cudaEventRecord(ev_g2, s_side);
    gemm_kernel<M_SIM><<<dim3(2, 2, NGRP), 256, SMEM_T3, s_side>>>(nullptr, nullptr, nullptr);
    cudaEventRecord(ev_sim, s_side);

    // main: G1 (128x128, K-slab 64, 2 CTA/SM)
    cudaStreamWaitEvent(0, ev_prep, 0);
    gemm_bf16_kernel<M_G1><<<dim3(32, 128), 256, SMEM_BF>>>(b_h, nullptr, nullptr);

    // main: LKV (bf16; needs vb from G1, lkhb from G2)
    cudaStreamWaitEvent(0, ev_g2, 0);
    gemm_lkv_kernel<<<dim3(16, 1, 16), 256, SMEM_LKV>>>();
    lkv_reduce_kernel<<<(4*QKD*HIDD)/256, 256>>>();

    // main: fused QUAD+LOUT (bf16; needs attnb, lkvb, gate, lqb)
    cudaStreamWaitEvent(0, ev_sim, 0);
    gemm_ql_kernel<<<dim3(16, 2, NGRP), 256, SMEM_QL>>>();

    // main: FIN (K-slab 64)
    gemm_bf16_kernel<M_FIN><<<dim3(8, 128), 256, SMEM_BF>>>(b_out, x, out);
}